// round 11
// baseline (speedup 1.0000x reference)
#include <cuda_runtime.h>
#include <cuda_fp16.h>
#include <stdint.h>
#include <math.h>

#define BB 2
#define LL 2048
#define DD 2048
#define HH 32
#define KVHN 8
#define PP 64
#define CONVD 3072
#define GDIM 2048
#define PROJD 5152
#define PROJP 5248   // padded row stride
#define CHUNK 128
#define NCH 16
#define BL 4096      // BB*LL

// ---------------- scratch (device globals: alloc-free) ----------------
__device__ __align__(256) float g_proj[(size_t)BL * PROJP];
__device__ __align__(256) float g_x[(size_t)BL * HH * PP];
__device__ __align__(256) float g_q[(size_t)BL * HH * PP];
__device__ __align__(256) float g_k[(size_t)BL * KVHN * PP];
__device__ __align__(256) float g_dt[(size_t)BL * HH];
__device__ __align__(256) float g_acs[(size_t)BL * HH];
__device__ __align__(256) float g_cdecay[BB * HH * NCH];
__device__ __align__(256) float g_states[(size_t)BB * NCH * HH * PP * PP];
__device__ __align__(256) float g_prefix[(size_t)BB * NCH * HH * PP * PP];
__device__ __align__(256) float g_y[(size_t)BL * HH * PP];

// gemm1 operands (all fp16)
__device__ __align__(256) __half g_hsf[(size_t)BL * DD];     // hs fp16 hi
__device__ __align__(256) __half g_hsfl[(size_t)BL * DD];    // hs fp16 lo
__device__ __align__(256) __half g_w1f[(size_t)CONVD * DD];  // W1 vkq rows fp16
__device__ __align__(256) __half g_w1g[(size_t)GDIM * DD];   // W1 gate rows fp16
__device__ __align__(256) __half g_wdth[(size_t)128 * DD];   // W1 dt rows (padded) fp16 hi
__device__ __align__(256) __half g_wdtl[(size_t)128 * DD];   // W1 dt rows (padded) fp16 lo
// gemm2 operands (fp16 1-pass)
__device__ __align__(256) __half g_woh[(size_t)DD * DD];
__device__ __align__(256) __half g_ygh[(size_t)BL * DD];

// ---------------- helpers ----------------
__device__ __forceinline__ uint32_t smem_u32(const void* p) {
    return (uint32_t)__cvta_generic_to_shared(p);
}
__device__ __forceinline__ void cpa16(uint32_t dst, const void* src) {
    asm volatile("cp.async.cg.shared.global [%0], [%1], 16;" :: "r"(dst), "l"(src) : "memory");
}
#define CP_COMMIT() asm volatile("cp.async.commit_group;" ::: "memory")
#define CP_WAIT(n)  asm volatile("cp.async.wait_group %0;" :: "n"(n) : "memory")

#define LDSM4(r, addr) \
    asm volatile("ldmatrix.sync.aligned.m8n8.x4.shared.b16 {%0,%1,%2,%3}, [%4];" \
        : "=r"((r)[0]), "=r"((r)[1]), "=r"((r)[2]), "=r"((r)[3]) : "r"(addr))

__device__ __forceinline__ void mma_f16(float* d, const uint32_t* a, uint32_t b0, uint32_t b1) {
    asm volatile("mma.sync.aligned.m16n8k16.row.col.f32.f16.f16.f32 "
        "{%0,%1,%2,%3}, {%4,%5,%6,%7}, {%8,%9}, {%0,%1,%2,%3};"
        : "+f"(d[0]), "+f"(d[1]), "+f"(d[2]), "+f"(d[3])
        : "r"(a[0]), "r"(a[1]), "r"(a[2]), "r"(a[3]), "r"(b0), "r"(b1));
}

// ---------------- fp32 -> fp16 splits ----------------
__device__ __forceinline__ void split4_hf(const float* v, uint2& ph, uint2& pl) {
    unsigned short h[4], l[4];
#pragma unroll
    for (int j = 0; j < 4; j++) {
        __half hb = __float2half_rn(v[j]);
        float r = v[j] - __half2float(hb);
        __half lb = __float2half_rn(r);
        h[j] = *(unsigned short*)&hb;
        l[j] = *(unsigned short*)&lb;
    }
    ph.x = (uint32_t)h[0] | ((uint32_t)h[1] << 16);
    ph.y = (uint32_t)h[2] | ((uint32_t)h[3] << 16);
    pl.x = (uint32_t)l[0] | ((uint32_t)l[1] << 16);
    pl.y = (uint32_t)l[2] | ((uint32_t)l[3] << 16);
}

__device__ __forceinline__ uint2 pack4_hf(const float* v) {
    __half2 a = __floats2half2_rn(v[0], v[1]);
    __half2 b = __floats2half2_rn(v[2], v[3]);
    return make_uint2(*(uint32_t*)&a, *(uint32_t*)&b);
}

// hs -> fp16 hi/lo
__global__ void k_cvt_hs(const float4* __restrict__ src, uint2* __restrict__ fh,
                         uint2* __restrict__ fl, int n4)
{
    int i = blockIdx.x * 256 + threadIdx.x;
    if (i >= n4) return;
    float4 v = src[i];
    float a[4] = {v.x, v.y, v.z, v.w};
    uint2 ph, pl;
    split4_hf(a, ph, pl);
    fh[i] = ph;
    fl[i] = pl;
}

// W1 rows [0,3072) -> fp16 (w1f) ; rows [3072,5120) -> fp16 (w1g)
__global__ void k_cvt_w1(const float4* __restrict__ W1, uint2* __restrict__ w1f,
                         uint2* __restrict__ w1g)
{
    const int NV = CONVD * DD / 4;
    const int NT = (CONVD + GDIM) * DD / 4;
    int i = blockIdx.x * 256 + threadIdx.x;
    if (i >= NT) return;
    float4 v = W1[i];
    float a[4] = {v.x, v.y, v.z, v.w};
    if (i < NV) w1f[i] = pack4_hf(a);
    else        w1g[i - NV] = pack4_hf(a);
}

// W1 dt rows -> fp16 hi/lo, zero-padded to 128 rows
__global__ void k_cvt_pad(const float4* __restrict__ src, uint2* __restrict__ hi,
                          uint2* __restrict__ lo, int n4s, int n4d)
{
    int i = blockIdx.x * 256 + threadIdx.x;
    if (i >= n4d) return;
    uint2 ph = make_uint2(0u, 0u), pl = make_uint2(0u, 0u);
    if (i < n4s) {
        float4 v = src[i];
        float a[4] = {v.x, v.y, v.z, v.w};
        split4_hf(a, ph, pl);
    }
    hi[i] = ph;
    lo[i] = pl;
}

__global__ void k_cvt_h(const float4* __restrict__ src, uint2* __restrict__ hi, int n4)
{
    int i = blockIdx.x * 256 + threadIdx.x;
    if (i >= n4) return;
    float4 v = src[i];
    float a[4] = {v.x, v.y, v.z, v.w};
    hi[i] = pack4_hf(a);
}

// ---------------- gemm1_g: gate (fp16 1-pass) + dt (fp16 3-pass, fused softplus) -----
// grid (17, 32). bx 0..15: gate -> proj cols [3072 + bx*128); bx 16: dt -> g_dt
#define STAGE1 65536
#define NSTG1 3

__global__ void __launch_bounds__(256) gemm1_g(
    const __half* __restrict__ Ahf, const __half* __restrict__ Alf,
    const __half* __restrict__ W1g,
    const __half* __restrict__ Wdth, const __half* __restrict__ Wdtl,
    const float* __restrict__ dt_bias,
    float* __restrict__ C)
{
    extern __shared__ char smem[];
    const int t = threadIdx.x;
    const int lane = t & 31;
    const int w = t >> 5;
    const int wm = w >> 2;
    const int wn = w & 3;
    const int bx = blockIdx.x;
    const int m0 = blockIdx.y * 128;
    uint32_t sbase = smem_u32(smem);

    const int mode = (bx == 16) ? 0 : 1;   // 0 = dt 3-pass, 1 = gate 1-pass
    const __half *Bh, *Bl = nullptr;
    int col0 = CONVD + bx * 128;
    if (mode == 0) { Bh = Wdth; Bl = Wdtl; }
    else           { Bh = W1g + (size_t)bx * 128 * DD; }

    const int mbase = wm * 64 + (lane & 15);
    const uint32_t a_k16 = (uint32_t)((lane >> 4) << 4);
    uint32_t a_off[4];
#pragma unroll
    for (int mt = 0; mt < 4; mt++) a_off[mt] = (uint32_t)((mbase + mt * 16) * 128);
    const uint32_t a_swz = (uint32_t)((mbase & 7) << 4);

    const int nbase = wn * 32 + (lane & 7) + ((lane >> 4) << 3);
    const uint32_t b_k16 = (uint32_t)(((lane >> 3) & 1) << 4);
    uint32_t b_off[2] = {(uint32_t)(nbase * 128), (uint32_t)((nbase + 16) * 128)};
    const uint32_t b_swz = (uint32_t)((nbase & 7) << 4);

    float acc[4][4][4];
#pragma unroll
    for (int i = 0; i < 4; i++)
#pragma unroll
        for (int j = 0; j < 4; j++)
#pragma unroll
            for (int r = 0; r < 4; r++) acc[i][j][r] = 0.f;

    const int NIT = DD >> 6;

    auto load_st = [&](uint32_t sb, int k0) {
#pragma unroll
        for (int u = 0; u < 4; u++) {
            int idx = t + u * 256;
            int row = idx >> 3, c16 = idx & 7;
            uint32_t so = (uint32_t)(row * 128) + (uint32_t)((c16 * 16) ^ ((row & 7) << 4));
            size_t gA = (size_t)(m0 + row) * DD + k0 + c16 * 8;
            size_t gB = (size_t)row * DD + k0 + c16 * 8;
            if (mode == 0) {
                cpa16(sb + so,         Ahf + gA);
                cpa16(sb + 16384 + so, Alf + gA);
                cpa16(sb + 32768 + so, Bh + gB);
                cpa16(sb + 49152 + so, Bl + gB);
            } else {
                cpa16(sb + so,         Ahf + gA);
                cpa16(sb + 32768 + so, Bh + gB);
            }
        }
    };

#pragma unroll
    for (int p = 0; p < NSTG1 - 1; p++) {
        load_st(sbase + p * STAGE1, p * 64);
        CP_COMMIT();
    }

    uint32_t ah[2][4][4], al[2][4][4], bh[2][2][4], bl[2][2][4];

    auto ldsm_frags = [&](int buf, uint32_t sb, int ks) {
        const uint32_t ka = ((uint32_t)(ks * 32) + a_k16) ^ a_swz;
        const uint32_t kb = ((uint32_t)(ks * 32) + b_k16) ^ b_swz;
#pragma unroll
        for (int mt = 0; mt < 4; mt++) LDSM4(ah[buf][mt], sb + a_off[mt] + ka);
        if (mode == 0) {
#pragma unroll
            for (int mt = 0; mt < 4; mt++) LDSM4(al[buf][mt], sb + 16384 + a_off[mt] + ka);
        }
#pragma unroll
        for (int n2 = 0; n2 < 2; n2++) LDSM4(bh[buf][n2], sb + 32768 + b_off[n2] + kb);
        if (mode == 0) {
#pragma unroll
            for (int n2 = 0; n2 < 2; n2++) LDSM4(bl[buf][n2], sb + 49152 + b_off[n2] + kb);
        }
    };
    auto mmas = [&](int buf) {
        if (mode == 0) {
#pragma unroll
            for (int mt = 0; mt < 4; mt++)
#pragma unroll
                for (int nt = 0; nt < 4; nt++)
                    mma_f16(acc[mt][nt], ah[buf][mt], bh[buf][nt >> 1][(nt & 1) * 2], bh[buf][nt >> 1][(nt & 1) * 2 + 1]);
#pragma unroll
            for (int mt = 0; mt < 4; mt++)
#pragma unroll
                for (int nt = 0; nt < 4; nt++)
                    mma_f16(acc[mt][nt], ah[buf][mt], bl[buf][nt >> 1][(nt & 1) * 2], bl[buf][nt >> 1][(nt & 1) * 2 + 1]);
#pragma unroll
            for (int mt = 0; mt < 4; mt++)
#pragma unroll
                for (int nt = 0; nt < 4; nt++)
                    mma_f16(acc[mt][nt], al[buf][mt], bh[buf][nt >> 1][(nt & 1) * 2], bh[buf][nt >> 1][(nt & 1) * 2 + 1]);
        } else {
#pragma unroll
            for (int mt = 0; mt < 4; mt++)
#pragma unroll
                for (int nt = 0; nt < 4; nt++)
                    mma_f16(acc[mt][nt], ah[buf][mt], bh[buf][nt >> 1][(nt & 1) * 2], bh[buf][nt >> 1][(nt & 1) * 2 + 1]);
        }
    };

    for (int it = 0; it < NIT; ++it) {
        CP_WAIT(NSTG1 - 2);
        __syncthreads();
        if (it + NSTG1 - 1 < NIT)
            load_st(sbase + ((it + NSTG1 - 1) % NSTG1) * STAGE1, (it + NSTG1 - 1) * 64);
        CP_COMMIT();

        uint32_t sb = sbase + (it % NSTG1) * STAGE1;
        ldsm_frags(0, sb, 0);
#pragma unroll
        for (int ks = 0; ks < 4; ks++) {
            if (ks < 3) ldsm_frags((ks + 1) & 1, sb, ks + 1);
            mmas(ks & 1);
        }
    }

    const int group = lane >> 2, tid4 = lane & 3;
    if (mode == 0) {
        // fused dt epilogue: softplus(val + dt_bias) -> g_dt [bl, h]; only cols < 32
        if (wn == 0) {
#pragma unroll
            for (int mt = 0; mt < 4; mt++) {
                int row = m0 + wm * 64 + mt * 16 + group;
#pragma unroll
                for (int nt = 0; nt < 4; nt++) {
                    int c = nt * 8 + tid4 * 2;   // 0..30
                    float b0 = dt_bias[c], b1 = dt_bias[c + 1];
                    float v00 = acc[mt][nt][0] + b0, v01 = acc[mt][nt][1] + b1;
                    float v10 = acc[mt][nt][2] + b0, v11 = acc[mt][nt][3] + b1;
                    v00 = (v00 > 20.f) ? v00 : log1pf(expf(v00));
                    v01 = (v01 > 20.f) ? v01 : log1pf(expf(v01));
                    v10 = (v10 > 20.f) ? v10 : log1pf(expf(v10));
                    v11 = (v11 > 20.f) ? v11 : log1pf(expf(v11));
                    g_dt[(size_t)row * HH + c]           = v00;
                    g_dt[(size_t)row * HH + c + 1]       = v01;
                    g_dt[(size_t)(row + 8) * HH + c]     = v10;
                    g_dt[(size_t)(row + 8) * HH + c + 1] = v11;
                }
            }
        }
    } else {
#pragma unroll
        for (int mt = 0; mt < 4; mt++) {
            int row = m0 + wm * 64 + mt * 16 + group;
#pragma unroll
            for (int nt = 0; nt < 4; nt++) {
                int col = col0 + wn * 32 + nt * 8 + tid4 * 2;
                *(float2*)(C + (size_t)row * PROJP + col) = make_float2(acc[mt][nt][0], acc[mt][nt][1]);
                *(float2*)(C + (size_t)(row + 8) * PROJP + col) = make_float2(acc[mt][nt][2], acc[mt][nt][3]);
            }
        }
    }
}

// ---------------- gemm1_f16: fp16 2-pass for v,k,q tiles (cols [0,3072)) -------------
// grid (24, 32). col0 = bx*128.
#define STAGEF 49152
#define NSTGF 4

__global__ void __launch_bounds__(256) gemm1_f16(
    const __half* __restrict__ Ah, const __half* __restrict__ Al,
    const __half* __restrict__ W1f, float* __restrict__ C)
{
    extern __shared__ char smem[];
    const int t = threadIdx.x;
    const int lane = t & 31;
    const int w = t >> 5;
    const int wm = w >> 2;
    const int wn = w & 3;
    const int m0 = blockIdx.y * 128;
    const int col0 = blockIdx.x * 128;
    const __half* Bh = W1f + (size_t)blockIdx.x * 128 * DD;
    uint32_t sbase = smem_u32(smem);

    const int mbase = wm * 64 + (lane & 15);
    const uint32_t a_k16 = (uint32_t)((lane >> 4) << 4);
    uint32_t a_off[4];
#pragma unroll
    for (int mt = 0; mt < 4; mt++) a_off[mt] = (uint32_t)((mbase + mt * 16) * 128);
    const uint32_t a_swz = (uint32_t)((mbase & 7) << 4);

    const int nbase = wn * 32 + (lane & 7) + ((lane >> 4) << 3);
    const uint32_t b_k16 = (uint32_t)(((lane >> 3) & 1) << 4);
    uint32_t b_off[2] = {(uint32_t)(nbase * 128), (uint32_t)((nbase + 16) * 128)};
    const uint32_t b_swz = (uint32_t)((nbase & 7) << 4);

    float acc[4][4][4];
#pragma unroll
    for (int i = 0; i < 4; i++)
#pragma unroll
        for (int j = 0; j < 4; j++)
#pragma unroll
            for (int r = 0; r < 4; r++) acc[i][j][r] = 0.f;

    const int NIT = DD >> 6;

    auto load_st = [&](uint32_t sb, int k0) {
#pragma unroll
        for (int u = 0; u < 4; u++) {
            int idx = t + u * 256;
            int row = idx >> 3, c16 = idx & 7;
            uint32_t so = (uint32_t)(row * 128) + (uint32_t)((c16 * 16) ^ ((row & 7) << 4));
            size_t gA = (size_t)(m0 + row) * DD + k0 + c16 * 8;
            size_t gB = (size_t)row * DD + k0 + c16 * 8;
            cpa16(sb + so,         Ah + gA);
            cpa16(sb + 16384 + so, Al + gA);
            cpa16(sb + 32768 + so, Bh + gB);
        }
    };

#pragma unroll
    for (int p = 0; p < NSTGF - 1; p++) {
        load_st(sbase + p * STAGEF, p * 64);
        CP_COMMIT();
    }

    uint32_t ah[2][4][4], al[2][4][4], bh[2][2][4];

    auto ldsm_frags = [&](int buf, uint32_t sb, int ks) {
        const uint32_t ka = ((uint32_t)(ks * 32) + a_k16) ^ a_swz;
        const uint32_t kb = ((uint32_t)(ks * 32) + b_k16) ^ b_swz;
#pragma unroll
        for (int mt = 0; mt < 4; mt++) LDSM4(ah[buf][mt], sb + a_off[mt] + ka);
#pragma unroll
        for (int mt = 0; mt < 4; mt++) LDSM4(al[buf][mt], sb + 16384 + a_off[mt] + ka);
#pragma unroll
        for (int n2 = 0; n2 < 2; n2++) LDSM4(bh[buf][n2], sb + 32768 + b_off[n2] + kb);
    };
    auto mmas = [&](int buf) {
#pragma unroll
        for (int mt = 0; mt < 4; mt++)
#pragma unroll
            for (int nt = 0; nt < 4; nt++)
                mma_f16(acc[mt][nt], ah[buf][mt], bh[buf][nt >> 1][(nt & 1) * 2], bh[buf][nt >> 1][(nt & 1) * 2 + 1]);
#pragma unroll
        for (int mt = 0; mt < 4; mt++)
#pragma unroll
            for (int nt = 0; nt < 4; nt++)
                mma_f16(acc[mt][nt], al[buf][mt], bh[buf][nt >> 1][(nt & 1) * 2], bh[buf][nt >> 1][(nt & 1) * 2 + 1]);
    };

    for (int it = 0; it < NIT; ++it) {
        CP_WAIT(NSTGF - 2);
        __syncthreads();
        if (it + NSTGF - 1 < NIT)
            load_st(sbase + ((it + NSTGF - 1) % NSTGF) * STAGEF, (it + NSTGF - 1) * 64);
        CP_COMMIT();

        uint32_t sb = sbase + (it % NSTGF) * STAGEF;
        ldsm_frags(0, sb, 0);
#pragma unroll
        for (int ks = 0; ks < 4; ks++) {
            if (ks < 3) ldsm_frags((ks + 1) & 1, sb, ks + 1);
            mmas(ks & 1);
        }
    }

    const int group = lane >> 2, tid4 = lane & 3;
#pragma unroll
    for (int mt = 0; mt < 4; mt++) {
        int row = m0 + wm * 64 + mt * 16 + group;
#pragma unroll
        for (int nt = 0; nt < 4; nt++) {
            int col = col0 + wn * 32 + nt * 8 + tid4 * 2;
            *(float2*)(C + (size_t)row * PROJP + col) = make_float2(acc[mt][nt][0], acc[mt][nt][1]);
            *(float2*)(C + (size_t)(row + 8) * PROJP + col) = make_float2(acc[mt][nt][2], acc[mt][nt][3]);
        }
    }
}

// ---------------- gemm2: fp16 1-pass ----------------
#define STAGE2 32768
#define NSTG2 5

__global__ void __launch_bounds__(256) gemm2(
    const __half* __restrict__ Ah, const __half* __restrict__ Bh, float* __restrict__ C)
{
    extern __shared__ char smem[];
    const int t = threadIdx.x;
    const int lane = t & 31;
    const int w = t >> 5;
    const int wm = w >> 2;
    const int wn = w & 3;
    const int m0 = blockIdx.y * 128;
    const int n0 = blockIdx.x * 128;
    uint32_t sbase = smem_u32(smem);

    const int mbase = wm * 64 + (lane & 15);
    const uint32_t a_k16 = (uint32_t)((lane >> 4) << 4);
    uint32_t a_off[4];
#pragma unroll
    for (int mt = 0; mt < 4; mt++) a_off[mt] = (uint32_t)((mbase + mt * 16) * 128);
    const uint32_t a_swz = (uint32_t)((mbase & 7) << 4);

    const int nbase = wn * 32 + (lane & 7) + ((lane >> 4) << 3);
    const uint32_t b_k16 = (uint32_t)(((lane >> 3) & 1) << 4);
    uint32_t b_off[2] = {(uint32_t)(nbase * 128), (uint32_t)((nbase + 16) * 128)};
    const uint32_t b_swz = (uint32_t)((nbase & 7) << 4);

    float acc[4][4][4];
#pragma unroll
    for (int i = 0; i < 4; i++)
#pragma unroll
        for (int j = 0; j < 4; j++)
#pragma unroll
            for (int r = 0; r < 4; r++) acc[i][j][r] = 0.f;

    const int NIT = DD >> 6;

    auto load_st = [&](uint32_t sb, int k0) {
#pragma unroll
        for (int u = 0; u < 4; u++) {
            int idx = t + u * 256;
            int row = idx >> 3, c16 = idx & 7;
            uint32_t so = (uint32_t)(row * 128) + (uint32_t)((c16 * 16) ^ ((row & 7) << 4));
            size_t gA = (size_t)(m0 + row) * DD + k0 + c16 * 8;
            size_t gB = (size_t)(n0 + row) * DD + k0 + c16 * 8;
            cpa16(sb + so,         Ah + gA);
            cpa16(sb + 16384 + so, Bh + gB);
        }
    };

#pragma unroll
    for (int p = 0; p < NSTG2 - 1; p++) {
        load_st(sbase + p * STAGE2, p * 64);
        CP_COMMIT();
    }

    uint32_t ah[2][4][4], bh[2][2][4];

    auto ldsm_frags = [&](int buf, uint32_t sb, int ks) {
        const uint32_t ka = ((uint32_t)(ks * 32) + a_k16) ^ a_swz;
        const uint32_t kb = ((uint32_t)(ks * 32) + b_k16) ^ b_swz;
#pragma unroll
        for (int mt = 0; mt < 4; mt++) LDSM4(ah[buf][mt], sb + a_off[mt] + ka);
#pragma unroll
        for (int n2 = 0; n2 < 2; n2++) LDSM4(bh[buf][n2], sb + 16384 + b_off[n2] + kb);
    };
    auto mmas = [&](int buf) {
#pragma unroll
        for (int mt = 0; mt < 4; mt++)
#pragma unroll
            for (int nt = 0; nt < 4; nt++)
                mma_f16(acc[mt][nt], ah[buf][mt], bh[buf][nt >> 1][(nt & 1) * 2], bh[buf][nt >> 1][(nt & 1) * 2 + 1]);
    };

    for (int it = 0; it < NIT; ++it) {
        CP_WAIT(NSTG2 - 2);
        __syncthreads();
        if (it + NSTG2 - 1 < NIT)
            load_st(sbase + ((it + NSTG2 - 1) % NSTG2) * STAGE2, (it + NSTG2 - 1) * 64);
        CP_COMMIT();

        uint32_t sb = sbase + (it % NSTG2) * STAGE2;
        ldsm_frags(0, sb, 0);
#pragma unroll
        for (int ks = 0; ks < 4; ks++) {
            if (ks < 3) ldsm_frags((ks + 1) & 1, sb, ks + 1);
            mmas(ks & 1);
        }
    }

    const int group = lane >> 2, tid4 = lane & 3;
#pragma unroll
    for (int mt = 0; mt < 4; mt++) {
        int row = m0 + wm * 64 + mt * 16 + group;
#pragma unroll
        for (int nt = 0; nt < 4; nt++) {
            int col = n0 + wn * 32 + nt * 8 + tid4 * 2;
            *(float2*)(C + (size_t)row * DD + col) = make_float2(acc[mt][nt][0], acc[mt][nt][1]);
            *(float2*)(C + (size_t)(row + 8) * DD + col) = make_float2(acc[mt][nt][2], acc[mt][nt][3]);
        }
    }
}

// ---------------- depthwise conv(k=2) + SiLU + route splits (vectorized x4) ----------------
__global__ void k_conv(const float* __restrict__ cw, const float* __restrict__ cb)
{
    const int C4 = CONVD / 4;   // 768
    int tid = blockIdx.x * 256 + threadIdx.x;
    if (tid >= BL * C4) return;
    int c = (tid % C4) * 4;
    int bl = tid / C4;
    int l = bl & (LL - 1);
    float4 cur = *(const float4*)(g_proj + (size_t)bl * PROJP + c);
    float4 prev = l ? *(const float4*)(g_proj + (size_t)(bl - 1) * PROJP + c)
                    : make_float4(0.f, 0.f, 0.f, 0.f);
    float4 w0 = *(const float4*)(cw + 2 * c);
    float4 w1 = *(const float4*)(cw + 2 * c + 4);
    float4 bb = *(const float4*)(cb + c);
    float v[4];
    v[0] = prev.x * w0.x + cur.x * w0.y + bb.x;
    v[1] = prev.y * w0.z + cur.y * w0.w + bb.y;
    v[2] = prev.z * w1.x + cur.z * w1.y + bb.z;
    v[3] = prev.w * w1.z + cur.w * w1.w + bb.w;
#pragma unroll
    for (int j = 0; j < 4; j++) v[j] = v[j] / (1.f + expf(-v[j]));

    if (c < KVHN * PP) {                       // v channels
        int kv = c >> 6, p = c & 63;
#pragma unroll
        for (int g = 0; g < 4; g++) {
            int h = kv * 4 + g;
            float dt = g_dt[(size_t)bl * HH + h];
            *(float4*)(g_x + ((size_t)bl * HH + h) * PP + p) =
                make_float4(v[0] * dt, v[1] * dt, v[2] * dt, v[3] * dt);
        }
    } else if (c < 2 * KVHN * PP) {            // k channels
        int cc = c - KVHN * PP;
        int kv = cc >> 6, p = cc & 63;
        *(float4*)(g_k + ((size_t)bl * KVHN + kv) * PP + p) =
            make_float4(v[0], v[1], v[2], v[3]);
    } else {                                   // q channels
        int cc = c - 2 * KVHN * PP;
        int h = cc >> 6, p = cc & 63;
        *(float4*)(g_q + ((size_t)bl * HH + h) * PP + p) =
            make_float4(v[0], v[1], v[2], v[3]);
    }
}

// ---------------- per-chunk cumsum of A*dt ----------------
__global__ void k_cumsum(const float* __restrict__ A_log_bias)
{
    int w = blockIdx.x * 8 + (threadIdx.x >> 5);
    int lane = threadIdx.x & 31;
    int c = w % NCH;
    int bh = w / NCH;
    int h = bh % HH;
    int b = bh / HH;
    float Ahv = -expf(A_log_bias[h]);
    int bl0 = b * LL + c * CHUNK;
    float v[4];
    float s = 0.f;
#pragma unroll
    for (int j = 0; j < 4; j++) {
        v[j] = g_dt[(size_t)(bl0 + lane * 4 + j) * HH + h] * Ahv;
        s += v[j];
    }
    float run = s;
#pragma unroll
    for (int d = 1; d < 32; d <<= 1) {
        float o = __shfl_up_sync(0xffffffffu, run, d);
        if (lane >= d) run += o;
    }
    float acc = run - s;
#pragma unroll
    for (int j = 0; j < 4; j++) {
        acc += v[j];
        g_acs[(size_t)(bl0 + lane * 4 + j) * HH + h] = acc;
    }
    if (lane == 31) g_cdecay[(b * HH + h) * NCH + c] = expf(acc);
}

// ---------------- Phase A: intra-chunk attention + chunk states ----------------
__global__ void __launch_bounds__(256) k_intra()
{
    extern __shared__ float sm[];
    float* sqT  = sm;
    float* skT  = sqT + 64 * 132;
    float* sS   = skT + 64 * 132;
    float* sx   = sS + 128 * 132;
    float* sacs = sx + 128 * 68;
    float* sei  = sacs + 128;
    float* sr   = sei + 128;
    float* sd   = sr + 128;

    const int t = threadIdx.x;
    const int h = blockIdx.x;
    const int c = blockIdx.y;
    const int b = blockIdx.z;
    const int bl0 = b * LL + c * CHUNK;
    const int kv = h >> 2;

    {
        int i = t >> 1;
        int n0 = (t & 1) * 32;
        const float* qp = g_q + ((size_t)(bl0 + i) * HH + h) * PP + n0;
        const float* kp = g_k + ((size_t)(bl0 + i) * KVHN + kv) * PP + n0;
        const float* xp = g_x + ((size_t)(bl0 + i) * HH + h) * PP + n0;
#pragma unroll
        for (int s = 0; s < 32; s += 4) {
            float4 vq = *(const float4*)(qp + s);
            sqT[(n0+s+0)*132 + i] = vq.x; sqT[(n0+s+1)*132 + i] = vq.y;
            sqT[(n0+s+2)*132 + i] = vq.z; sqT[(n0+s+3)*132 + i] = vq.w;
            float4 vk = *(const float4*)(kp + s);
            skT[(n0+s+0)*132 + i] = vk.x; skT[(n0+s+1)*132 + i] = vk.y;
            skT[(n0+s+2)*132 + i] = vk.z; skT[(n0+s+3)*132 + i] = vk.w;
            *(float4*)&sx[i * 68 + n0 + s] = *(const float4*)(xp + s);
        }
        if (t < 128) sacs[t] = g_acs[(size_t)(bl0 + t) * HH + h];
    }
    __syncthreads();
    if (t < 128) {
        float a = sacs[t];
        sei[t] = expf(a);
        sr[t]  = expf(fminf(-a, 80.f));
        sd[t]  = expf(sacs[127] - a);
    }
    __syncthreads();

    {
        const int i0 = (t >> 4) * 8;
        const int j0 = (t & 15) * 8;
        float accS[8][8];
#pragma unroll
        for (int i = 0; i < 8; i++)
#pragma unroll
            for (int j = 0; j < 8; j++) accS[i][j] = 0.f;
#pragma unroll 8
        for (int kk = 0; kk < 64; kk++) {
            float ar[8], br[8];
            *(float4*)(ar)     = *(const float4*)&sqT[kk * 132 + i0];
            *(float4*)(ar + 4) = *(const float4*)&sqT[kk * 132 + i0 + 4];
            *(float4*)(br)     = *(const float4*)&skT[kk * 132 + j0];
            *(float4*)(br + 4) = *(const float4*)&skT[kk * 132 + j0 + 4];
#pragma unroll
            for (int i = 0; i < 8; i++)
#pragma unroll
                for (int j = 0; j < 8; j++)
                    accS[i][j] = fmaf(ar[i], br[j], accS[i][j]);
        }
#pragma unroll
        for (int ii = 0; ii < 8; ii++) {
            int i = i0 + ii;
            float e_i = sei[i];
#pragma unroll
            for (int jj = 0; jj < 8; jj++) {
                int j = j0 + jj;
                sS[i * 132 + j] = (j <= i) ? accS[ii][jj] * e_i * sr[j] : 0.f;
            }
        }
    }
    __syncthreads();

    {
        const int i0 = (t >> 4) * 8;
        const int p0 = (t & 15) * 4;
        const int jmax = i0 + 8;   // strictly causal clamp
        float accY[8][4];
#pragma unroll
        for (int i = 0; i < 8; i++)
#pragma unroll
            for (int j = 0; j < 4; j++) accY[i][j] = 0.f;
#pragma unroll 4
        for (int j = 0; j < jmax; j++) {
            float4 xv = *(const float4*)&sx[j * 68 + p0];
#pragma unroll
            for (int ii = 0; ii < 8; ii++) {
                float s = sS[(i0 + ii) * 132 + j];
                accY[ii][0] = fmaf(s, xv.x, accY[ii][0]);
                accY[ii][1] = fmaf(s, xv.y, accY[ii][1]);
                accY[ii][2] = fmaf(s, xv.z, accY[ii][2]);
                accY[ii][3] = fmaf(s, xv.w, accY[ii][3]);
            }
        }
#pragma unroll
        for (int ii = 0; ii < 8; ii++) {
            *(float4*)(g_y + ((size_t)(bl0 + i0 + ii) * HH + h) * PP + p0) =
                make_float4(accY[ii][0], accY[ii][1], accY[ii][2], accY[ii][3]);
        }
    }

    {
        const int n0 = (t >> 4) * 4;
        const int p0 = (t & 15) * 4;
        float accT[4][4];
#pragma unroll
        for (int i = 0; i < 4; i++)
#pragma unroll
            for (int j = 0; j < 4; j++) accT[i][j] = 0.f;
#pragma unroll 4
        for (int j = 0; j < 128; j++) {
            float dj = sd[j];
            float4 xv = *(const float4*)&sx[j * 68 + p0];
            float xd[4] = {xv.x * dj, xv.y * dj, xv.z * dj, xv.w * dj};
#pragma unroll
            for (int nn = 0; nn < 4; nn++) {
                float kvv = skT[(n0 + nn) * 132 + j];
                accT[nn][0] = fmaf(kvv, xd[0], accT[nn][0]);
                accT[nn][1] = fmaf(kvv, xd[1], accT[nn][1]);
                accT[nn][2] = fmaf(kvv, xd[2], accT[nn][2]);
                accT[nn][3] = fmaf(kvv, xd[3], accT[nn][3]);
            }
        }
        size_t base = (((size_t)(b * NCH + c) * HH + h) << 12);
#pragma unroll
        for (int nn = 0; nn < 4; nn++) {
            *(float4*)(g_states + base + (size_t)(n0 + nn) * PP + p0) =
                make_float4(accT[nn][0], accT[nn][1], accT[nn][2], accT[nn][3]);
        }
    }
}

// ---------------- Phase B: inter-chunk state scan (1 chain / thread) ----------------
__global__ void k_scan()
{
    const int e = blockIdx.x * 256 + threadIdx.x;   // 0..4095
    const int h = blockIdx.y;
    const int b = blockIdx.z;
    const float* dec = g_cdecay + (b * HH + h) * NCH;
    float run = 0.f;
#pragma unroll
    for (int c = 0; c < NCH; c++) {
        size_t off = (((size_t)(b * NCH + c) * HH + h) << 12) + e;
        g_prefix[off] = run;
        run = run * dec[c] + g_states[off];
    }
}

// ---------------- Phase C: inter-chunk output + RMSNorm + gate (emit fp16) ----------------
__global__ void __launch_bounds__(256) k_inter(const float* __restrict__ gnw)
{
    __shared__ float spref[64 * 64];
    __shared__ float sacs[128];
    const int t = threadIdx.x;
    const int h = blockIdx.x;
    const int c = blockIdx.y;
    const int b = blockIdx.z;
    const int bl0 = b * LL + c * CHUNK;
    size_t pbase = (((size_t)(b * NCH + c) * HH + h) << 12);
    for (int e = t; e < 4096; e += 256) spref[e] = g_prefix[pbase + e];
    if (t < 128) sacs[t] = g_acs[(size_t)(bl0 + t) * HH + h];
    __syncthreads();

    const int i = t >> 1;
    const int p0 = (t & 1) * 32;
    const int bl = bl0 + i;
    const float4* qp = (const float4*)(g_q + ((size_t)bl * HH + h) * PP);

    float acc[32];
#pragma unroll
    for (int pp = 0; pp < 32; pp++) acc[pp] = 0.f;
#pragma unroll
    for (int nb = 0; nb < 16; nb++) {
        float4 qv = qp[nb];
        float qa[4] = {qv.x, qv.y, qv.z, qv.w};
#pragma unroll
        for (int e = 0; e < 4; e++) {
            const float* pr = &spref[(nb * 4 + e) * 64 + p0];
#pragma unroll
            for (int pp = 0; pp < 32; pp += 4) {
                float4 pv = *(const float4*)(pr + pp);
                acc[pp+0] = fmaf(qa[e], pv.x, acc[pp+0]);
                acc[pp+1] = fmaf(qa[e], pv.y, acc[pp+1]);
                acc[pp+2] = fmaf(qa[e], pv.z, acc[pp+2]);
                acc[pp+3] = fmaf(qa[e], pv.w, acc[pp+3]);
            }
        }
    }

    float ei = expf(sacs[i]);
    const float4* ydp = (const float4*)(g_y + ((size_t)bl * HH + h) * PP + p0);
    float y[32];
    float ss = 0.f;
#pragma unroll
    for (int pp = 0; pp < 32; pp += 4) {
        float4 yv = ydp[pp >> 2];
        y[pp+0] = yv.x + ei * acc[pp+0];
        y[pp+1] = yv.y + ei * acc[pp+1];
        y[pp+2] = yv.z + ei * acc[pp+2];
        y[pp+3] = yv.w + ei * acc[pp+3];
        ss += y[pp+0]*y[pp+0] + y[pp+1]*y[pp+1] + y[pp+2]*y[pp+2] + y[pp+3]*y[pp+3];
    }
    ss += __shfl_xor_sync(0xffffffffu, ss, 1);
    float scale = rsqrtf(ss * (1.f / 64.f) + 1e-5f);

    const float* gp = g_proj + (size_t)bl * PROJP + CONVD + h * PP + p0;
    size_t obase = (size_t)bl * DD + h * PP + p0;
#pragma unroll
    for (int pp = 0; pp < 32; pp += 4) {
        float ov[4];
#pragma unroll
        for (int j = 0; j < 4; j++) {
            float gv = gp[pp + j];
            float sg = gv / (1.f + expf(-gv));
            ov[j] = y[pp + j] * scale * gnw[p0 + pp + j] * sg;
        }
        *(uint2*)(g_ygh + obase + pp) = pack4_hf(ov);
    }
}

// ---------------- launch ----------------
extern "C" void kernel_launch(void* const* d_in, const int* in_sizes, int n_in,
                              void* d_out, int out_size)
{
    const float* hs       = (const float*)d_in[0];
    const float* W1       = (const float*)d_in[1];
    const float* conv_w   = (const float*)d_in[2];
    const float* conv_b   = (const float*)d_in[3];
    const float* dt_bias  = (const float*)d_in[4];
    const float* A_logb   = (const float*)d_in[5];
    const float* gnorm_w  = (const float*)d_in[6];
    const float* W_o      = (const float*)d_in[7];
    float* out = (float*)d_out;

    float *p_proj;
    __half *p_hsf, *p_hsfl, *p_w1f, *p_w1g, *p_wdth, *p_wdtl, *p_woh, *p_ygh;
    cudaGetSymbolAddress((void**)&p_proj, g_proj);
    cudaGetSymbolAddress((void**)&p_hsf, g_hsf);
    cudaGetSymbolAddress((void**)&p_hsfl, g_hsfl);
    cudaGetSymbolAddress((void**)&p_w1f, g_w1f);
    cudaGetSymbolAddress((void**)&p_w1g, g_w1g);
    cudaGetSymbolAddress((void**)&p_wdth, g_wdth);
    cudaGetSymbolAddress((void**)&p_wdtl, g_wdtl);
    cudaGetSymbolAddress((void**)&p_woh, g_woh);
    cudaGetSymbolAddress((void**)&p_ygh, g_ygh);

    cudaFuncSetAttribute(k_intra, cudaFuncAttributeMaxDynamicSharedMemorySize, 172032);
    cudaFuncSetAttribute(gemm1_g, cudaFuncAttributeMaxDynamicSharedMemorySize, NSTG1 * STAGE1);
    cudaFuncSetAttribute(gemm1_f16, cudaFuncAttributeMaxDynamicSharedMemorySize, NSTGF * STAGEF);
    cudaFuncSetAttribute(gemm2, cudaFuncAttributeMaxDynamicSharedMemorySize, NSTG2 * STAGE2);

    // operand conversions (all fp16)
    k_cvt_hs<<<(BL * DD / 4 + 255) / 256, 256>>>((const float4*)hs,
                                                 (uint2*)p_hsf, (uint2*)p_hsfl, BL * DD / 4);
    k_cvt_w1<<<((CONVD + GDIM) * DD / 4 + 255) / 256, 256>>>((const float4*)W1,
                                                 (uint2*)p_w1f, (uint2*)p_w1g);
    k_cvt_pad<<<(128 * DD / 4 + 255) / 256, 256>>>((const float4*)(W1 + (size_t)(CONVD + GDIM) * DD),
                                                   (uint2*)p_wdth, (uint2*)p_wdtl,
                                                   32 * DD / 4, 128 * DD / 4);
    k_cvt_h<<<(DD * DD / 4 + 255) / 256, 256>>>((const float4*)W_o, (uint2*)p_woh, DD * DD / 4);

    // 1a. v,k,q (fp16 2-pass, cols [0,3072))
    gemm1_f16<<<dim3(24, BL / 128), 256, NSTGF * STAGEF>>>(p_hsf, p_hsfl, p_w1f, p_proj);
    // 1b. gate + dt (fp16 1-pass / fp16 3-pass + fused softplus)
    gemm1_g<<<dim3(17, BL / 128), 256, NSTG1 * STAGE1>>>(
        p_hsf, p_hsfl, p_w1g, p_wdth, p_wdtl, dt_bias, p_proj);

    // 2..6 SSD pipeline
    k_conv<<<(BL * (CONVD / 4) + 255) / 256, 256>>>(conv_w, conv_b);
    k_cumsum<<<128, 256>>>(A_logb);
    k_intra<<<dim3(HH, NCH, BB), 256, 172032>>>();
    k_scan<<<dim3(16, HH, BB), 256>>>();
    k_inter<<<dim3(HH, NCH, BB), 256>>>(gnorm_w);

    // 7. out = yg @ Wo^T (fp16 1-pass)
    gemm2<<<dim3(DD / 128, BL / 128), 256, NSTG2 * STAGE2>>>(p_ygh, p_woh, out);
}

// round 12
// speedup vs baseline: 1.4845x; 1.4845x over previous
#include <cuda_runtime.h>
#include <cuda_bf16.h>
#include <cuda_fp16.h>
#include <stdint.h>
#include <math.h>

#define BB 2
#define LL 2048
#define DD 2048
#define HH 32
#define KVHN 8
#define PP 64
#define CONVD 3072
#define GDIM 2048
#define PROJD 5152
#define PROJP 5248   // padded row stride
#define CHUNK 128
#define NCH 16
#define BL 4096      // BB*LL

// ---------------- scratch (device globals: alloc-free) ----------------
__device__ __align__(256) float g_proj[(size_t)BL * PROJP];
__device__ __align__(256) float g_x[(size_t)BL * HH * PP];
__device__ __align__(256) float g_q[(size_t)BL * HH * PP];
__device__ __align__(256) float g_k[(size_t)BL * KVHN * PP];
__device__ __align__(256) float g_dt[(size_t)BL * HH];
__device__ __align__(256) float g_acs[(size_t)BL * HH];
__device__ __align__(256) float g_cdecay[BB * HH * NCH];
__device__ __align__(256) float g_states[(size_t)BB * NCH * HH * PP * PP];
__device__ __align__(256) float g_prefix[(size_t)BB * NCH * HH * PP * PP];
__device__ __align__(256) float g_y[(size_t)BL * HH * PP];

// gemm1 operands
__device__ __align__(256) __nv_bfloat16 g_hsh[(size_t)BL * DD];     // hs bf16 hi
__device__ __align__(256) __nv_bfloat16 g_hsl[(size_t)BL * DD];     // hs bf16 lo
__device__ __align__(256) __half        g_hsf[(size_t)BL * DD];     // hs fp16 hi
__device__ __align__(256) __half        g_hsfl[(size_t)BL * DD];    // hs fp16 lo
__device__ __align__(256) __nv_bfloat16 g_w1h[(size_t)CONVD * DD];  // W1 vkq bf16 hi (k rows used)
__device__ __align__(256) __nv_bfloat16 g_w1l[(size_t)CONVD * DD];  // W1 vkq bf16 lo
__device__ __align__(256) __half        g_w1f[(size_t)CONVD * DD];  // W1 vkq fp16 (v,q rows used)
__device__ __align__(256) __half        g_w1g[(size_t)GDIM * DD];   // W1 gate fp16
__device__ __align__(256) __nv_bfloat16 g_wdth[(size_t)128 * DD];
__device__ __align__(256) __nv_bfloat16 g_wdtl[(size_t)128 * DD];
// gemm2 operands (fp16 1-pass)
__device__ __align__(256) __half g_woh[(size_t)DD * DD];
__device__ __align__(256) __half g_ygh[(size_t)BL * DD];

// ---------------- helpers ----------------
__device__ __forceinline__ uint32_t smem_u32(const void* p) {
    return (uint32_t)__cvta_generic_to_shared(p);
}
__device__ __forceinline__ void cpa16(uint32_t dst, const void* src) {
    asm volatile("cp.async.cg.shared.global [%0], [%1], 16;" :: "r"(dst), "l"(src) : "memory");
}
#define CP_COMMIT() asm volatile("cp.async.commit_group;" ::: "memory")
#define CP_WAIT(n)  asm volatile("cp.async.wait_group %0;" :: "n"(n) : "memory")

#define LDSM4(r, addr) \
    asm volatile("ldmatrix.sync.aligned.m8n8.x4.shared.b16 {%0,%1,%2,%3}, [%4];" \
        : "=r"((r)[0]), "=r"((r)[1]), "=r"((r)[2]), "=r"((r)[3]) : "r"(addr))

__device__ __forceinline__ void mma_bf16(float* d, const uint32_t* a, uint32_t b0, uint32_t b1) {
    asm volatile("mma.sync.aligned.m16n8k16.row.col.f32.bf16.bf16.f32 "
        "{%0,%1,%2,%3}, {%4,%5,%6,%7}, {%8,%9}, {%0,%1,%2,%3};"
        : "+f"(d[0]), "+f"(d[1]), "+f"(d[2]), "+f"(d[3])
        : "r"(a[0]), "r"(a[1]), "r"(a[2]), "r"(a[3]), "r"(b0), "r"(b1));
}
__device__ __forceinline__ void mma_f16(float* d, const uint32_t* a, uint32_t b0, uint32_t b1) {
    asm volatile("mma.sync.aligned.m16n8k16.row.col.f32.f16.f16.f32 "
        "{%0,%1,%2,%3}, {%4,%5,%6,%7}, {%8,%9}, {%0,%1,%2,%3};"
        : "+f"(d[0]), "+f"(d[1]), "+f"(d[2]), "+f"(d[3])
        : "r"(a[0]), "r"(a[1]), "r"(a[2]), "r"(a[3]), "r"(b0), "r"(b1));
}

// ---------------- fp32 -> bf16 / fp16 splits ----------------
__device__ __forceinline__ void split4_bf(const float* v, uint2& ph, uint2& pl) {
    unsigned short h[4], l[4];
#pragma unroll
    for (int j = 0; j < 4; j++) {
        __nv_bfloat16 hb = __float2bfloat16(v[j]);
        float r = v[j] - __bfloat162float(hb);
        __nv_bfloat16 lb = __float2bfloat16(r);
        h[j] = *(unsigned short*)&hb;
        l[j] = *(unsigned short*)&lb;
    }
    ph.x = (uint32_t)h[0] | ((uint32_t)h[1] << 16);
    ph.y = (uint32_t)h[2] | ((uint32_t)h[3] << 16);
    pl.x = (uint32_t)l[0] | ((uint32_t)l[1] << 16);
    pl.y = (uint32_t)l[2] | ((uint32_t)l[3] << 16);
}
__device__ __forceinline__ void split4_hf(const float* v, uint2& ph, uint2& pl) {
    unsigned short h[4], l[4];
#pragma unroll
    for (int j = 0; j < 4; j++) {
        __half hb = __float2half_rn(v[j]);
        float r = v[j] - __half2float(hb);
        __half lb = __float2half_rn(r);
        h[j] = *(unsigned short*)&hb;
        l[j] = *(unsigned short*)&lb;
    }
    ph.x = (uint32_t)h[0] | ((uint32_t)h[1] << 16);
    ph.y = (uint32_t)h[2] | ((uint32_t)h[3] << 16);
    pl.x = (uint32_t)l[0] | ((uint32_t)l[1] << 16);
    pl.y = (uint32_t)l[2] | ((uint32_t)l[3] << 16);
}

__device__ __forceinline__ uint2 pack4_hf(const float* v) {
    __half2 a = __floats2half2_rn(v[0], v[1]);
    __half2 b = __floats2half2_rn(v[2], v[3]);
    return make_uint2(*(uint32_t*)&a, *(uint32_t*)&b);
}

// hs -> bf16 hi/lo + fp16 hi/lo (one read)
__global__ void k_cvt_hs(const float4* __restrict__ src, uint2* __restrict__ bh,
                         uint2* __restrict__ bl, uint2* __restrict__ fh,
                         uint2* __restrict__ fl, int n4)
{
    int i = blockIdx.x * 256 + threadIdx.x;
    if (i >= n4) return;
    float4 v = src[i];
    float a[4] = {v.x, v.y, v.z, v.w};
    uint2 ph, pl;
    split4_bf(a, ph, pl);
    bh[i] = ph;
    bl[i] = pl;
    split4_hf(a, ph, pl);
    fh[i] = ph;
    fl[i] = pl;
}

// W1 rows [0,3072) -> bf16 hi/lo + fp16 ; rows [3072,5120) -> fp16 gate
__global__ void k_cvt_w1(const float4* __restrict__ W1, uint2* __restrict__ w1h,
                         uint2* __restrict__ w1l, uint2* __restrict__ w1f,
                         uint2* __restrict__ w1g)
{
    const int NV = CONVD * DD / 4;
    const int NT = (CONVD + GDIM) * DD / 4;
    int i = blockIdx.x * 256 + threadIdx.x;
    if (i >= NT) return;
    float4 v = W1[i];
    float a[4] = {v.x, v.y, v.z, v.w};
    if (i < NV) {
        uint2 ph, pl;
        split4_bf(a, ph, pl);
        w1h[i] = ph;
        w1l[i] = pl;
        w1f[i] = pack4_hf(a);
    } else {
        w1g[i - NV] = pack4_hf(a);
    }
}

__global__ void k_cvt_pad(const float4* __restrict__ src, uint2* __restrict__ hi,
                          uint2* __restrict__ lo, int n4s, int n4d)
{
    int i = blockIdx.x * 256 + threadIdx.x;
    if (i >= n4d) return;
    uint2 ph = make_uint2(0u, 0u), pl = make_uint2(0u, 0u);
    if (i < n4s) {
        float4 v = src[i];
        float a[4] = {v.x, v.y, v.z, v.w};
        split4_bf(a, ph, pl);
    }
    hi[i] = ph;
    lo[i] = pl;
}

__global__ void k_cvt_h(const float4* __restrict__ src, uint2* __restrict__ hi, int n4)
{
    int i = blockIdx.x * 256 + threadIdx.x;
    if (i >= n4) return;
    float4 v = src[i];
    float a[4] = {v.x, v.y, v.z, v.w};
    hi[i] = pack4_hf(a);
}

// ---------------- gemm1_bf: 2-mode (bf16 3-pass / fp16 1-pass) ----
// grid (21, 32).
//   bx 0..3  : k    -> bf16 3-pass (mode 0), proj cols [512 + bx*128)
//   bx 4..19 : gate -> fp16 1-pass (mode 1), proj cols [3072 + (bx-4)*128)
//   bx 20    : dt   -> bf16 3-pass (mode 0) + fused softplus -> g_dt
#define STAGE1 65536
#define NSTG1 3

__global__ void __launch_bounds__(256) gemm1_bf(
    const __nv_bfloat16* __restrict__ Ahb, const __nv_bfloat16* __restrict__ Alb,
    const __half* __restrict__ Ahf,
    const __nv_bfloat16* __restrict__ W1h, const __nv_bfloat16* __restrict__ W1l,
    const __half* __restrict__ W1g,
    const __nv_bfloat16* __restrict__ Wdth, const __nv_bfloat16* __restrict__ Wdtl,
    const float* __restrict__ dt_bias,
    float* __restrict__ C)
{
    extern __shared__ char smem[];
    const int t = threadIdx.x;
    const int lane = t & 31;
    const int w = t >> 5;
    const int wm = w >> 2;
    const int wn = w & 3;
    const int bx = blockIdx.x;
    const int m0 = blockIdx.y * 128;
    uint32_t sbase = smem_u32(smem);

    const int mode = (bx < 4 || bx == 20) ? 0 : 1;
    int col0;
    const __nv_bfloat16 *Bh = nullptr, *Bl = nullptr;
    const __half *Bf = nullptr;
    if (bx < 4) {
        Bh = W1h + (size_t)(bx + 4) * 128 * DD;
        Bl = W1l + (size_t)(bx + 4) * 128 * DD;
        col0 = (bx + 4) * 128;
    } else if (bx < 20) {
        Bf = W1g + (size_t)(bx - 4) * 128 * DD;
        col0 = CONVD + (bx - 4) * 128;
    } else {
        Bh = Wdth; Bl = Wdtl;
        col0 = CONVD + GDIM;   // unused (fused epilogue)
    }

    const int mbase = wm * 64 + (lane & 15);
    const uint32_t a_k16 = (uint32_t)((lane >> 4) << 4);
    uint32_t a_off[4];
#pragma unroll
    for (int mt = 0; mt < 4; mt++) a_off[mt] = (uint32_t)((mbase + mt * 16) * 128);
    const uint32_t a_swz = (uint32_t)((mbase & 7) << 4);

    const int nbase = wn * 32 + (lane & 7) + ((lane >> 4) << 3);
    const uint32_t b_k16 = (uint32_t)(((lane >> 3) & 1) << 4);
    uint32_t b_off[2] = {(uint32_t)(nbase * 128), (uint32_t)((nbase + 16) * 128)};
    const uint32_t b_swz = (uint32_t)((nbase & 7) << 4);

    float acc[4][4][4];
#pragma unroll
    for (int i = 0; i < 4; i++)
#pragma unroll
        for (int j = 0; j < 4; j++)
#pragma unroll
            for (int r = 0; r < 4; r++) acc[i][j][r] = 0.f;

    const int NIT = DD >> 6;

    auto load_st = [&](uint32_t sb, int k0) {
#pragma unroll
        for (int u = 0; u < 4; u++) {
            int idx = t + u * 256;
            int row = idx >> 3, c16 = idx & 7;
            uint32_t so = (uint32_t)(row * 128) + (uint32_t)((c16 * 16) ^ ((row & 7) << 4));
            size_t gA = (size_t)(m0 + row) * DD + k0 + c16 * 8;
            size_t gB = (size_t)row * DD + k0 + c16 * 8;
            if (mode == 0) {
                cpa16(sb + so,         Ahb + gA);
                cpa16(sb + 16384 + so, Alb + gA);
                cpa16(sb + 32768 + so, Bh + gB);
                cpa16(sb + 49152 + so, Bl + gB);
            } else {
                cpa16(sb + so,         Ahf + gA);
                cpa16(sb + 32768 + so, Bf + gB);
            }
        }
    };

#pragma unroll
    for (int p = 0; p < NSTG1 - 1; p++) {
        load_st(sbase + p * STAGE1, p * 64);
        CP_COMMIT();
    }

    uint32_t ah[2][4][4], al[2][4][4], bh[2][2][4], bl[2][2][4];

    auto ldsm_frags = [&](int buf, uint32_t sb, int ks) {
        const uint32_t ka = ((uint32_t)(ks * 32) + a_k16) ^ a_swz;
        const uint32_t kb = ((uint32_t)(ks * 32) + b_k16) ^ b_swz;
#pragma unroll
        for (int mt = 0; mt < 4; mt++) LDSM4(ah[buf][mt], sb + a_off[mt] + ka);
        if (mode == 0) {
#pragma unroll
            for (int mt = 0; mt < 4; mt++) LDSM4(al[buf][mt], sb + 16384 + a_off[mt] + ka);
        }
#pragma unroll
        for (int n2 = 0; n2 < 2; n2++) LDSM4(bh[buf][n2], sb + 32768 + b_off[n2] + kb);
        if (mode == 0) {
#pragma unroll
            for (int n2 = 0; n2 < 2; n2++) LDSM4(bl[buf][n2], sb + 49152 + b_off[n2] + kb);
        }
    };
    auto mmas = [&](int buf) {
        if (mode == 0) {
#pragma unroll
            for (int mt = 0; mt < 4; mt++)
#pragma unroll
                for (int nt = 0; nt < 4; nt++)
                    mma_bf16(acc[mt][nt], ah[buf][mt], bh[buf][nt >> 1][(nt & 1) * 2], bh[buf][nt >> 1][(nt & 1) * 2 + 1]);
#pragma unroll
            for (int mt = 0; mt < 4; mt++)
#pragma unroll
                for (int nt = 0; nt < 4; nt++)
                    mma_bf16(acc[mt][nt], ah[buf][mt], bl[buf][nt >> 1][(nt & 1) * 2], bl[buf][nt >> 1][(nt & 1) * 2 + 1]);
#pragma unroll
            for (int mt = 0; mt < 4; mt++)
#pragma unroll
                for (int nt = 0; nt < 4; nt++)
                    mma_bf16(acc[mt][nt], al[buf][mt], bh[buf][nt >> 1][(nt & 1) * 2], bh[buf][nt >> 1][(nt & 1) * 2 + 1]);
        } else {
#pragma unroll
            for (int mt = 0; mt < 4; mt++)
#pragma unroll
                for (int nt = 0; nt < 4; nt++)
                    mma_f16(acc[mt][nt], ah[buf][mt], bh[buf][nt >> 1][(nt & 1) * 2], bh[buf][nt >> 1][(nt & 1) * 2 + 1]);
        }
    };

    for (int it = 0; it < NIT; ++it) {
        CP_WAIT(NSTG1 - 2);
        __syncthreads();
        if (it + NSTG1 - 1 < NIT)
            load_st(sbase + ((it + NSTG1 - 1) % NSTG1) * STAGE1, (it + NSTG1 - 1) * 64);
        CP_COMMIT();

        uint32_t sb = sbase + (it % NSTG1) * STAGE1;
        ldsm_frags(0, sb, 0);
#pragma unroll
        for (int ks = 0; ks < 4; ks++) {
            if (ks < 3) ldsm_frags((ks + 1) & 1, sb, ks + 1);
            mmas(ks & 1);
        }
    }

    const int group = lane >> 2, tid4 = lane & 3;
    if (bx == 20) {
        // fused dt epilogue: softplus(val + dt_bias) -> g_dt [bl, h]; only cols < 32
        if (wn == 0) {
#pragma unroll
            for (int mt = 0; mt < 4; mt++) {
                int row = m0 + wm * 64 + mt * 16 + group;
#pragma unroll
                for (int nt = 0; nt < 4; nt++) {
                    int c = nt * 8 + tid4 * 2;   // 0..30
                    float b0 = dt_bias[c], b1 = dt_bias[c + 1];
                    float v00 = acc[mt][nt][0] + b0, v01 = acc[mt][nt][1] + b1;
                    float v10 = acc[mt][nt][2] + b0, v11 = acc[mt][nt][3] + b1;
                    v00 = (v00 > 20.f) ? v00 : log1pf(expf(v00));
                    v01 = (v01 > 20.f) ? v01 : log1pf(expf(v01));
                    v10 = (v10 > 20.f) ? v10 : log1pf(expf(v10));
                    v11 = (v11 > 20.f) ? v11 : log1pf(expf(v11));
                    g_dt[(size_t)row * HH + c]           = v00;
                    g_dt[(size_t)row * HH + c + 1]       = v01;
                    g_dt[(size_t)(row + 8) * HH + c]     = v10;
                    g_dt[(size_t)(row + 8) * HH + c + 1] = v11;
                }
            }
        }
    } else {
#pragma unroll
        for (int mt = 0; mt < 4; mt++) {
            int row = m0 + wm * 64 + mt * 16 + group;
#pragma unroll
            for (int nt = 0; nt < 4; nt++) {
                int col = col0 + wn * 32 + nt * 8 + tid4 * 2;
                *(float2*)(C + (size_t)row * PROJP + col) = make_float2(acc[mt][nt][0], acc[mt][nt][1]);
                *(float2*)(C + (size_t)(row + 8) * PROJP + col) = make_float2(acc[mt][nt][2], acc[mt][nt][3]);
            }
        }
    }
}

// ---------------- gemm1_f16: fp16 2-pass for v + q tiles ----------
// grid (20, 32). bx 0..3 -> v tile bx; bx 4..19 -> q tile bx+4.
#define STAGEF 49152
#define NSTGF 4

__global__ void __launch_bounds__(256) gemm1_f16(
    const __half* __restrict__ Ah, const __half* __restrict__ Al,
    const __half* __restrict__ W1f, float* __restrict__ C)
{
    extern __shared__ char smem[];
    const int t = threadIdx.x;
    const int lane = t & 31;
    const int w = t >> 5;
    const int wm = w >> 2;
    const int wn = w & 3;
    const int tile = (blockIdx.x < 4) ? blockIdx.x : blockIdx.x + 4;
    const int m0 = blockIdx.y * 128;
    const int col0 = tile * 128;
    const __half* Bh = W1f + (size_t)tile * 128 * DD;
    uint32_t sbase = smem_u32(smem);

    const int mbase = wm * 64 + (lane & 15);
    const uint32_t a_k16 = (uint32_t)((lane >> 4) << 4);
    uint32_t a_off[4];
#pragma unroll
    for (int mt = 0; mt < 4; mt++) a_off[mt] = (uint32_t)((mbase + mt * 16) * 128);
    const uint32_t a_swz = (uint32_t)((mbase & 7) << 4);

    const int nbase = wn * 32 + (lane & 7) + ((lane >> 4) << 3);
    const uint32_t b_k16 = (uint32_t)(((lane >> 3) & 1) << 4);
    uint32_t b_off[2] = {(uint32_t)(nbase * 128), (uint32_t)((nbase + 16) * 128)};
    const uint32_t b_swz = (uint32_t)((nbase & 7) << 4);

    float acc[4][4][4];
#pragma unroll
    for (int i = 0; i < 4; i++)
#pragma unroll
        for (int j = 0; j < 4; j++)
#pragma unroll
            for (int r = 0; r < 4; r++) acc[i][j][r] = 0.f;

    const int NIT = DD >> 6;

    auto load_st = [&](uint32_t sb, int k0) {
#pragma unroll
        for (int u = 0; u < 4; u++) {
            int idx = t + u * 256;
            int row = idx >> 3, c16 = idx & 7;
            uint32_t so = (uint32_t)(row * 128) + (uint32_t)((c16 * 16) ^ ((row & 7) << 4));
            size_t gA = (size_t)(m0 + row) * DD + k0 + c16 * 8;
            size_t gB = (size_t)row * DD + k0 + c16 * 8;
            cpa16(sb + so,         Ah + gA);
            cpa16(sb + 16384 + so, Al + gA);
            cpa16(sb + 32768 + so, Bh + gB);
        }
    };

#pragma unroll
    for (int p = 0; p < NSTGF - 1; p++) {
        load_st(sbase + p * STAGEF, p * 64);
        CP_COMMIT();
    }

    uint32_t ah[2][4][4], al[2][4][4], bh[2][2][4];

    auto ldsm_frags = [&](int buf, uint32_t sb, int ks) {
        const uint32_t ka = ((uint32_t)(ks * 32) + a_k16) ^ a_swz;
        const uint32_t kb = ((uint32_t)(ks * 32) + b_k16) ^ b_swz;
#pragma unroll
        for (int mt = 0; mt < 4; mt++) LDSM4(ah[buf][mt], sb + a_off[mt] + ka);
#pragma unroll
        for (int mt = 0; mt < 4; mt++) LDSM4(al[buf][mt], sb + 16384 + a_off[mt] + ka);
#pragma unroll
        for (int n2 = 0; n2 < 2; n2++) LDSM4(bh[buf][n2], sb + 32768 + b_off[n2] + kb);
    };
    auto mmas = [&](int buf) {
#pragma unroll
        for (int mt = 0; mt < 4; mt++)
#pragma unroll
            for (int nt = 0; nt < 4; nt++)
                mma_f16(acc[mt][nt], ah[buf][mt], bh[buf][nt >> 1][(nt & 1) * 2], bh[buf][nt >> 1][(nt & 1) * 2 + 1]);
#pragma unroll
        for (int mt = 0; mt < 4; mt++)
#pragma unroll
            for (int nt = 0; nt < 4; nt++)
                mma_f16(acc[mt][nt], al[buf][mt], bh[buf][nt >> 1][(nt & 1) * 2], bh[buf][nt >> 1][(nt & 1) * 2 + 1]);
    };

    for (int it = 0; it < NIT; ++it) {
        CP_WAIT(NSTGF - 2);
        __syncthreads();
        if (it + NSTGF - 1 < NIT)
            load_st(sbase + ((it + NSTGF - 1) % NSTGF) * STAGEF, (it + NSTGF - 1) * 64);
        CP_COMMIT();

        uint32_t sb = sbase + (it % NSTGF) * STAGEF;
        ldsm_frags(0, sb, 0);
#pragma unroll
        for (int ks = 0; ks < 4; ks++) {
            if (ks < 3) ldsm_frags((ks + 1) & 1, sb, ks + 1);
            mmas(ks & 1);
        }
    }

    const int group = lane >> 2, tid4 = lane & 3;
#pragma unroll
    for (int mt = 0; mt < 4; mt++) {
        int row = m0 + wm * 64 + mt * 16 + group;
#pragma unroll
        for (int nt = 0; nt < 4; nt++) {
            int col = col0 + wn * 32 + nt * 8 + tid4 * 2;
            *(float2*)(C + (size_t)row * PROJP + col) = make_float2(acc[mt][nt][0], acc[mt][nt][1]);
            *(float2*)(C + (size_t)(row + 8) * PROJP + col) = make_float2(acc[mt][nt][2], acc[mt][nt][3]);
        }
    }
}

// ---------------- gemm2: fp16 1-pass ----------------
#define STAGE2 32768
#define NSTG2 5

__global__ void __launch_bounds__(256) gemm2(
    const __half* __restrict__ Ah, const __half* __restrict__ Bh, float* __restrict__ C)
{
    extern __shared__ char smem[];
    const int t = threadIdx.x;
    const int lane = t & 31;
    const int w = t >> 5;
    const int wm = w >> 2;
    const int wn = w & 3;
    const int m0 = blockIdx.y * 128;
    const int n0 = blockIdx.x * 128;
    uint32_t sbase = smem_u32(smem);

    const int mbase = wm * 64 + (lane & 15);
    const uint32_t a_k16 = (uint32_t)((lane >> 4) << 4);
    uint32_t a_off[4];
#pragma unroll
    for (int mt = 0; mt < 4; mt++) a_off[mt] = (uint32_t)((mbase + mt * 16) * 128);
    const uint32_t a_swz = (uint32_t)((mbase & 7) << 4);

    const int nbase = wn * 32 + (lane & 7) + ((lane >> 4) << 3);
    const uint32_t b_k16 = (uint32_t)(((lane >> 3) & 1) << 4);
    uint32_t b_off[2] = {(uint32_t)(nbase * 128), (uint32_t)((nbase + 16) * 128)};
    const uint32_t b_swz = (uint32_t)((nbase & 7) << 4);

    float acc[4][4][4];
#pragma unroll
    for (int i = 0; i < 4; i++)
#pragma unroll
        for (int j = 0; j < 4; j++)
#pragma unroll
            for (int r = 0; r < 4; r++) acc[i][j][r] = 0.f;

    const int NIT = DD >> 6;

    auto load_st = [&](uint32_t sb, int k0) {
#pragma unroll
        for (int u = 0; u < 4; u++) {
            int idx = t + u * 256;
            int row = idx >> 3, c16 = idx & 7;
            uint32_t so = (uint32_t)(row * 128) + (uint32_t)((c16 * 16) ^ ((row & 7) << 4));
            size_t gA = (size_t)(m0 + row) * DD + k0 + c16 * 8;
            size_t gB = (size_t)(n0 + row) * DD + k0 + c16 * 8;
            cpa16(sb + so,         Ah + gA);
            cpa16(sb + 16384 + so, Bh + gB);
        }
    };

#pragma unroll
    for (int p = 0; p < NSTG2 - 1; p++) {
        load_st(sbase + p * STAGE2, p * 64);
        CP_COMMIT();
    }

    uint32_t ah[2][4][4], bh[2][2][4];

    auto ldsm_frags = [&](int buf, uint32_t sb, int ks) {
        const uint32_t ka = ((uint32_t)(ks * 32) + a_k16) ^ a_swz;
        const uint32_t kb = ((uint32_t)(ks * 32) + b_k16) ^ b_swz;
#pragma unroll
        for (int mt = 0; mt < 4; mt++) LDSM4(ah[buf][mt], sb + a_off[mt] + ka);
#pragma unroll
        for (int n2 = 0; n2 < 2; n2++) LDSM4(bh[buf][n2], sb + 16384 + b_off[n2] + kb);
    };
    auto mmas = [&](int buf) {
#pragma unroll
        for (int mt = 0; mt < 4; mt++)
#pragma unroll
            for (int nt = 0; nt < 4; nt++)
                mma_f16(acc[mt][nt], ah[buf][mt], bh[buf][nt >> 1][(nt & 1) * 2], bh[buf][nt >> 1][(nt & 1) * 2 + 1]);
    };

    for (int it = 0; it < NIT; ++it) {
        CP_WAIT(NSTG2 - 2);
        __syncthreads();
        if (it + NSTG2 - 1 < NIT)
            load_st(sbase + ((it + NSTG2 - 1) % NSTG2) * STAGE2, (it + NSTG2 - 1) * 64);
        CP_COMMIT();

        uint32_t sb = sbase + (it % NSTG2) * STAGE2;
        ldsm_frags(0, sb, 0);
#pragma unroll
        for (int ks = 0; ks < 4; ks++) {
            if (ks < 3) ldsm_frags((ks + 1) & 1, sb, ks + 1);
            mmas(ks & 1);
        }
    }

    const int group = lane >> 2, tid4 = lane & 3;
#pragma unroll
    for (int mt = 0; mt < 4; mt++) {
        int row = m0 + wm * 64 + mt * 16 + group;
#pragma unroll
        for (int nt = 0; nt < 4; nt++) {
            int col = n0 + wn * 32 + nt * 8 + tid4 * 2;
            *(float2*)(C + (size_t)row * DD + col) = make_float2(acc[mt][nt][0], acc[mt][nt][1]);
            *(float2*)(C + (size_t)(row + 8) * DD + col) = make_float2(acc[mt][nt][2], acc[mt][nt][3]);
        }
    }
}

// ---------------- depthwise conv(k=2) + SiLU + route splits (vectorized x4) ----------------
__global__ void k_conv(const float* __restrict__ cw, const float* __restrict__ cb)
{
    const int C4 = CONVD / 4;   // 768
    int tid = blockIdx.x * 256 + threadIdx.x;
    if (tid >= BL * C4) return;
    int c = (tid % C4) * 4;
    int bl = tid / C4;
    int l = bl & (LL - 1);
    float4 cur = *(const float4*)(g_proj + (size_t)bl * PROJP + c);
    float4 prev = l ? *(const float4*)(g_proj + (size_t)(bl - 1) * PROJP + c)
                    : make_float4(0.f, 0.f, 0.f, 0.f);
    float4 w0 = *(const float4*)(cw + 2 * c);
    float4 w1 = *(const float4*)(cw + 2 * c + 4);
    float4 bb = *(const float4*)(cb + c);
    float v[4];
    v[0] = prev.x * w0.x + cur.x * w0.y + bb.x;
    v[1] = prev.y * w0.z + cur.y * w0.w + bb.y;
    v[2] = prev.z * w1.x + cur.z * w1.y + bb.z;
    v[3] = prev.w * w1.z + cur.w * w1.w + bb.w;
#pragma unroll
    for (int j = 0; j < 4; j++) v[j] = v[j] / (1.f + expf(-v[j]));

    if (c < KVHN * PP) {                       // v channels
        int kv = c >> 6, p = c & 63;
#pragma unroll
        for (int g = 0; g < 4; g++) {
            int h = kv * 4 + g;
            float dt = g_dt[(size_t)bl * HH + h];
            *(float4*)(g_x + ((size_t)bl * HH + h) * PP + p) =
                make_float4(v[0] * dt, v[1] * dt, v[2] * dt, v[3] * dt);
        }
    } else if (c < 2 * KVHN * PP) {            // k channels
        int cc = c - KVHN * PP;
        int kv = cc >> 6, p = cc & 63;
        *(float4*)(g_k + ((size_t)bl * KVHN + kv) * PP + p) =
            make_float4(v[0], v[1], v[2], v[3]);
    } else {                                   // q channels
        int cc = c - 2 * KVHN * PP;
        int h = cc >> 6, p = cc & 63;
        *(float4*)(g_q + ((size_t)bl * HH + h) * PP + p) =
            make_float4(v[0], v[1], v[2], v[3]);
    }
}

// ---------------- per-chunk cumsum of A*dt ----------------
__global__ void k_cumsum(const float* __restrict__ A_log_bias)
{
    int w = blockIdx.x * 8 + (threadIdx.x >> 5);
    int lane = threadIdx.x & 31;
    int c = w % NCH;
    int bh = w / NCH;
    int h = bh % HH;
    int b = bh / HH;
    float Ahv = -expf(A_log_bias[h]);
    int bl0 = b * LL + c * CHUNK;
    float v[4];
    float s = 0.f;
#pragma unroll
    for (int j = 0; j < 4; j++) {
        v[j] = g_dt[(size_t)(bl0 + lane * 4 + j) * HH + h] * Ahv;
        s += v[j];
    }
    float run = s;
#pragma unroll
    for (int d = 1; d < 32; d <<= 1) {
        float o = __shfl_up_sync(0xffffffffu, run, d);
        if (lane >= d) run += o;
    }
    float acc = run - s;
#pragma unroll
    for (int j = 0; j < 4; j++) {
        acc += v[j];
        g_acs[(size_t)(bl0 + lane * 4 + j) * HH + h] = acc;
    }
    if (lane == 31) g_cdecay[(b * HH + h) * NCH + c] = expf(acc);
}

// ---------------- Phase A: intra-chunk attention + chunk states ----------------
__global__ void __launch_bounds__(256) k_intra()
{
    extern __shared__ float sm[];
    float* sqT  = sm;
    float* skT  = sqT + 64 * 132;
    float* sS   = skT + 64 * 132;
    float* sx   = sS + 128 * 132;
    float* sacs = sx + 128 * 68;
    float* sei  = sacs + 128;
    float* sr   = sei + 128;
    float* sd   = sr + 128;

    const int t = threadIdx.x;
    const int h = blockIdx.x;
    const int c = blockIdx.y;
    const int b = blockIdx.z;
    const int bl0 = b * LL + c * CHUNK;
    const int kv = h >> 2;

    {
        int i = t >> 1;
        int n0 = (t & 1) * 32;
        const float* qp = g_q + ((size_t)(bl0 + i) * HH + h) * PP + n0;
        const float* kp = g_k + ((size_t)(bl0 + i) * KVHN + kv) * PP + n0;
        const float* xp = g_x + ((size_t)(bl0 + i) * HH + h) * PP + n0;
#pragma unroll
        for (int s = 0; s < 32; s += 4) {
            float4 vq = *(const float4*)(qp + s);
            sqT[(n0+s+0)*132 + i] = vq.x; sqT[(n0+s+1)*132 + i] = vq.y;
            sqT[(n0+s+2)*132 + i] = vq.z; sqT[(n0+s+3)*132 + i] = vq.w;
            float4 vk = *(const float4*)(kp + s);
            skT[(n0+s+0)*132 + i] = vk.x; skT[(n0+s+1)*132 + i] = vk.y;
            skT[(n0+s+2)*132 + i] = vk.z; skT[(n0+s+3)*132 + i] = vk.w;
            *(float4*)&sx[i * 68 + n0 + s] = *(const float4*)(xp + s);
        }
        if (t < 128) sacs[t] = g_acs[(size_t)(bl0 + t) * HH + h];
    }
    __syncthreads();
    if (t < 128) {
        float a = sacs[t];
        sei[t] = expf(a);
        sr[t]  = expf(fminf(-a, 80.f));
        sd[t]  = expf(sacs[127] - a);
    }
    __syncthreads();

    {
        const int i0 = (t >> 4) * 8;
        const int j0 = (t & 15) * 8;
        float accS[8][8];
#pragma unroll
        for (int i = 0; i < 8; i++)
#pragma unroll
            for (int j = 0; j < 8; j++) accS[i][j] = 0.f;
#pragma unroll 8
        for (int kk = 0; kk < 64; kk++) {
            float ar[8], br[8];
            *(float4*)(ar)     = *(const float4*)&sqT[kk * 132 + i0];
            *(float4*)(ar + 4) = *(const float4*)&sqT[kk * 132 + i0 + 4];
            *(float4*)(br)     = *(const float4*)&skT[kk * 132 + j0];
            *(float4*)(br + 4) = *(const float4*)&skT[kk * 132 + j0 + 4];
#pragma unroll
            for (int i = 0; i < 8; i++)
#pragma unroll
                for (int j = 0; j < 8; j++)
                    accS[i][j] = fmaf(ar[i], br[j], accS[i][j]);
        }
#pragma unroll
        for (int ii = 0; ii < 8; ii++) {
            int i = i0 + ii;
            float e_i = sei[i];
#pragma unroll
            for (int jj = 0; jj < 8; jj++) {
                int j = j0 + jj;
                sS[i * 132 + j] = (j <= i) ? accS[ii][jj] * e_i * sr[j] : 0.f;
            }
        }
    }
    __syncthreads();

    {
        const int i0 = (t >> 4) * 8;
        const int p0 = (t & 15) * 4;
        const int jmax = i0 + 8;   // strictly causal clamp
        float accY[8][4];
#pragma unroll
        for (int i = 0; i < 8; i++)
#pragma unroll
            for (int j = 0; j < 4; j++) accY[i][j] = 0.f;
#pragma unroll 4
        for (int j = 0; j < jmax; j++) {
            float4 xv = *(const float4*)&sx[j * 68 + p0];
#pragma unroll
            for (int ii = 0; ii < 8; ii++) {
                float s = sS[(i0 + ii) * 132 + j];
                accY[ii][0] = fmaf(s, xv.x, accY[ii][0]);
                accY[ii][1] = fmaf(s, xv.y, accY[ii][1]);
                accY[ii][2] = fmaf(s, xv.z, accY[ii][2]);
                accY[ii][3] = fmaf(s, xv.w, accY[ii][3]);
            }
        }
#pragma unroll
        for (int ii = 0; ii < 8; ii++) {
            *(float4*)(g_y + ((size_t)(bl0 + i0 + ii) * HH + h) * PP + p0) =
                make_float4(accY[ii][0], accY[ii][1], accY[ii][2], accY[ii][3]);
        }
    }

    {
        const int n0 = (t >> 4) * 4;
        const int p0 = (t & 15) * 4;
        float accT[4][4];
#pragma unroll
        for (int i = 0; i < 4; i++)
#pragma unroll
            for (int j = 0; j < 4; j++) accT[i][j] = 0.f;
#pragma unroll 4
        for (int j = 0; j < 128; j++) {
            float dj = sd[j];
            float4 xv = *(const float4*)&sx[j * 68 + p0];
            float xd[4] = {xv.x * dj, xv.y * dj, xv.z * dj, xv.w * dj};
#pragma unroll
            for (int nn = 0; nn < 4; nn++) {
                float kvv = skT[(n0 + nn) * 132 + j];
                accT[nn][0] = fmaf(kvv, xd[0], accT[nn][0]);
                accT[nn][1] = fmaf(kvv, xd[1], accT[nn][1]);
                accT[nn][2] = fmaf(kvv, xd[2], accT[nn][2]);
                accT[nn][3] = fmaf(kvv, xd[3], accT[nn][3]);
            }
        }
        size_t base = (((size_t)(b * NCH + c) * HH + h) << 12);
#pragma unroll
        for (int nn = 0; nn < 4; nn++) {
            *(float4*)(g_states + base + (size_t)(n0 + nn) * PP + p0) =
                make_float4(accT[nn][0], accT[nn][1], accT[nn][2], accT[nn][3]);
        }
    }
}

// ---------------- Phase B: inter-chunk state scan (1 chain / thread) ----------------
__global__ void k_scan()
{
    const int e = blockIdx.x * 256 + threadIdx.x;   // 0..4095
    const int h = blockIdx.y;
    const int b = blockIdx.z;
    const float* dec = g_cdecay + (b * HH + h) * NCH;
    float run = 0.f;
#pragma unroll
    for (int c = 0; c < NCH; c++) {
        size_t off = (((size_t)(b * NCH + c) * HH + h) << 12) + e;
        g_prefix[off] = run;
        run = run * dec[c] + g_states[off];
    }
}

// ---------------- Phase C: inter-chunk output + RMSNorm + gate (emit fp16) ----------------
__global__ void __launch_bounds__(256) k_inter(const float* __restrict__ gnw)
{
    __shared__ float spref[64 * 64];
    __shared__ float sacs[128];
    const int t = threadIdx.x;
    const int h = blockIdx.x;
    const int c = blockIdx.y;
    const int b = blockIdx.z;
    const int bl0 = b * LL + c * CHUNK;
    size_t pbase = (((size_t)(b * NCH + c) * HH + h) << 12);
    for (int e = t; e < 4096; e += 256) spref[e] = g_prefix[pbase + e];
    if (t < 128) sacs[t] = g_acs[(size_t)(bl0 + t) * HH + h];
    __syncthreads();

    const int i = t >> 1;
    const int p0 = (t & 1) * 32;
    const int bl = bl0 + i;
    const float4* qp = (const float4*)(g_q + ((size_t)bl * HH + h) * PP);

    float acc[32];
#pragma unroll
    for (int pp = 0; pp < 32; pp++) acc[pp] = 0.f;
#pragma unroll
    for (int nb = 0; nb < 16; nb++) {
        float4 qv = qp[nb];
        float qa[4] = {qv.x, qv.y, qv.z, qv.w};
#pragma unroll
        for (int e = 0; e < 4; e++) {
            const float* pr = &spref[(nb * 4 + e) * 64 + p0];
#pragma unroll
            for (int pp = 0; pp < 32; pp += 4) {
                float4 pv = *(const float4*)(pr + pp);
                acc[pp+0] = fmaf(qa[e], pv.x, acc[pp+0]);
                acc[pp+1] = fmaf(qa[e], pv.y, acc[pp+1]);
                acc[pp+2] = fmaf(qa[e], pv.z, acc[pp+2]);
                acc[pp+3] = fmaf(qa[e], pv.w, acc[pp+3]);
            }
        }
    }

    float ei = expf(sacs[i]);
    const float4* ydp = (const float4*)(g_y + ((size_t)bl * HH + h) * PP + p0);
    float y[32];
    float ss = 0.f;
#pragma unroll
    for (int pp = 0; pp < 32; pp += 4) {
        float4 yv = ydp[pp >> 2];
        y[pp+0] = yv.x + ei * acc[pp+0];
        y[pp+1] = yv.y + ei * acc[pp+1];
        y[pp+2] = yv.z + ei * acc[pp+2];
        y[pp+3] = yv.w + ei * acc[pp+3];
        ss += y[pp+0]*y[pp+0] + y[pp+1]*y[pp+1] + y[pp+2]*y[pp+2] + y[pp+3]*y[pp+3];
    }
    ss += __shfl_xor_sync(0xffffffffu, ss, 1);
    float scale = rsqrtf(ss * (1.f / 64.f) + 1e-5f);

    const float* gp = g_proj + (size_t)bl * PROJP + CONVD + h * PP + p0;
    size_t obase = (size_t)bl * DD + h * PP + p0;
#pragma unroll
    for (int pp = 0; pp < 32; pp += 4) {
        float ov[4];
#pragma unroll
        for (int j = 0; j < 4; j++) {
            float gv = gp[pp + j];
            float sg = gv / (1.f + expf(-gv));
            ov[j] = y[pp + j] * scale * gnw[p0 + pp + j] * sg;
        }
        *(uint2*)(g_ygh + obase + pp) = pack4_hf(ov);
    }
}

// ---------------- launch ----------------
extern "C" void kernel_launch(void* const* d_in, const int* in_sizes, int n_in,
                              void* d_out, int out_size)
{
    const float* hs       = (const float*)d_in[0];
    const float* W1       = (const float*)d_in[1];
    const float* conv_w   = (const float*)d_in[2];
    const float* conv_b   = (const float*)d_in[3];
    const float* dt_bias  = (const float*)d_in[4];
    const float* A_logb   = (const float*)d_in[5];
    const float* gnorm_w  = (const float*)d_in[6];
    const float* W_o      = (const float*)d_in[7];
    float* out = (float*)d_out;

    float *p_proj;
    __nv_bfloat16 *p_hsh, *p_hsl, *p_w1h, *p_w1l, *p_wdth, *p_wdtl;
    __half *p_hsf, *p_hsfl, *p_w1f, *p_w1g, *p_woh, *p_ygh;
    cudaGetSymbolAddress((void**)&p_proj, g_proj);
    cudaGetSymbolAddress((void**)&p_hsh, g_hsh);
    cudaGetSymbolAddress((void**)&p_hsl, g_hsl);
    cudaGetSymbolAddress((void**)&p_hsf, g_hsf);
    cudaGetSymbolAddress((void**)&p_hsfl, g_hsfl);
    cudaGetSymbolAddress((void**)&p_w1h, g_w1h);
    cudaGetSymbolAddress((void**)&p_w1l, g_w1l);
    cudaGetSymbolAddress((void**)&p_w1f, g_w1f);
    cudaGetSymbolAddress((void**)&p_w1g, g_w1g);
    cudaGetSymbolAddress((void**)&p_wdth, g_wdth);
    cudaGetSymbolAddress((void**)&p_wdtl, g_wdtl);
    cudaGetSymbolAddress((void**)&p_woh, g_woh);
    cudaGetSymbolAddress((void**)&p_ygh, g_ygh);

    cudaFuncSetAttribute(k_intra, cudaFuncAttributeMaxDynamicSharedMemorySize, 172032);
    cudaFuncSetAttribute(gemm1_bf, cudaFuncAttributeMaxDynamicSharedMemorySize, NSTG1 * STAGE1);
    cudaFuncSetAttribute(gemm1_f16, cudaFuncAttributeMaxDynamicSharedMemorySize, NSTGF * STAGEF);
    cudaFuncSetAttribute(gemm2, cudaFuncAttributeMaxDynamicSharedMemorySize, NSTG2 * STAGE2);

    // operand conversions
    k_cvt_hs<<<(BL * DD / 4 + 255) / 256, 256>>>((const float4*)hs, (uint2*)p_hsh,
                                                 (uint2*)p_hsl, (uint2*)p_hsf,
                                                 (uint2*)p_hsfl, BL * DD / 4);
    k_cvt_w1<<<((CONVD + GDIM) * DD / 4 + 255) / 256, 256>>>((const float4*)W1,
                                                 (uint2*)p_w1h, (uint2*)p_w1l,
                                                 (uint2*)p_w1f, (uint2*)p_w1g);
    k_cvt_pad<<<(128 * DD / 4 + 255) / 256, 256>>>((const float4*)(W1 + (size_t)(CONVD + GDIM) * DD),
                                                   (uint2*)p_wdth, (uint2*)p_wdtl,
                                                   32 * DD / 4, 128 * DD / 4);
    k_cvt_h<<<(DD * DD / 4 + 255) / 256, 256>>>((const float4*)W_o, (uint2*)p_woh, DD * DD / 4);

    // 1a. k + gate + dt (2-mode, fused dt softplus)
    gemm1_bf<<<dim3(21, BL / 128), 256, NSTG1 * STAGE1>>>(
        p_hsh, p_hsl, p_hsf, p_w1h, p_w1l, p_w1g, p_wdth, p_wdtl, dt_bias, p_proj);
    // 1b. v + q (fp16 2-pass)
    gemm1_f16<<<dim3(20, BL / 128), 256, NSTGF * STAGEF>>>(
        p_hsf, p_hsfl, p_w1f, p_proj);

    // 2..6 SSD pipeline
    k_conv<<<(BL * (CONVD / 4) + 255) / 256, 256>>>(conv_w, conv_b);
    k_cumsum<<<128, 256>>>(A_logb);
    k_intra<<<dim3(HH, NCH, BB), 256, 172032>>>();
    k_scan<<<dim3(16, HH, BB), 256>>>();
    k_inter<<<dim3(HH, NCH, BB), 256>>>(gnorm_w);

    // 7. out = yg @ Wo^T (fp16 1-pass)
    gemm2<<<dim3(DD / 128, BL / 128), 256, NSTG2 * STAGE2>>>(p_ygh, p_woh, out);
}

// round 13
// speedup vs baseline: 1.5384x; 1.0363x over previous
#include <cuda_runtime.h>
#include <cuda_bf16.h>
#include <cuda_fp16.h>
#include <stdint.h>
#include <math.h>

#define BB 2
#define LL 2048
#define DD 2048
#define HH 32
#define KVHN 8
#define PP 64
#define CONVD 3072
#define GDIM 2048
#define PROJD 5152
#define PROJP 5248   // padded row stride
#define CHUNK 128
#define NCH 16
#define BL 4096      // BB*LL

// ---------------- scratch (device globals: alloc-free) ----------------
__device__ __align__(256) float g_proj[(size_t)BL * PROJP];
__device__ __align__(256) float g_x[(size_t)BL * HH * PP];
__device__ __align__(256) float g_q[(size_t)BL * HH * PP];
__device__ __align__(256) float g_k[(size_t)BL * KVHN * PP];
__device__ __align__(256) float g_dt[(size_t)BL * HH];
__device__ __align__(256) float g_acs[(size_t)BL * HH];
__device__ __align__(256) float g_cdecay[BB * HH * NCH];
__device__ __align__(256) float g_states[(size_t)BB * NCH * HH * PP * PP];
__device__ __align__(256) float g_prefix[(size_t)BB * NCH * HH * PP * PP];
__device__ __align__(256) float g_y[(size_t)BL * HH * PP];

// gemm1 operands
__device__ __align__(256) __nv_bfloat16 g_hsh[(size_t)BL * DD];     // hs bf16 hi (dt tile A)
__device__ __align__(256) __nv_bfloat16 g_hsl[(size_t)BL * DD];     // hs bf16 lo
__device__ __align__(256) __half        g_hsf[(size_t)BL * DD];     // hs fp16 hi
__device__ __align__(256) __half        g_hsfl[(size_t)BL * DD];    // hs fp16 lo
__device__ __align__(256) __half        g_w1f[(size_t)CONVD * DD];  // W1 vkq rows fp16
__device__ __align__(256) __half        g_w1g[(size_t)GDIM * DD];   // W1 gate fp16
__device__ __align__(256) __nv_bfloat16 g_wdth[(size_t)128 * DD];
__device__ __align__(256) __nv_bfloat16 g_wdtl[(size_t)128 * DD];
// gemm2 operands (fp16 1-pass)
__device__ __align__(256) __half g_woh[(size_t)DD * DD];
__device__ __align__(256) __half g_ygh[(size_t)BL * DD];

// ---------------- helpers ----------------
__device__ __forceinline__ uint32_t smem_u32(const void* p) {
    return (uint32_t)__cvta_generic_to_shared(p);
}
__device__ __forceinline__ void cpa16(uint32_t dst, const void* src) {
    asm volatile("cp.async.cg.shared.global [%0], [%1], 16;" :: "r"(dst), "l"(src) : "memory");
}
#define CP_COMMIT() asm volatile("cp.async.commit_group;" ::: "memory")
#define CP_WAIT(n)  asm volatile("cp.async.wait_group %0;" :: "n"(n) : "memory")

#define LDSM4(r, addr) \
    asm volatile("ldmatrix.sync.aligned.m8n8.x4.shared.b16 {%0,%1,%2,%3}, [%4];" \
        : "=r"((r)[0]), "=r"((r)[1]), "=r"((r)[2]), "=r"((r)[3]) : "r"(addr))

__device__ __forceinline__ void mma_bf16(float* d, const uint32_t* a, uint32_t b0, uint32_t b1) {
    asm volatile("mma.sync.aligned.m16n8k16.row.col.f32.bf16.bf16.f32 "
        "{%0,%1,%2,%3}, {%4,%5,%6,%7}, {%8,%9}, {%0,%1,%2,%3};"
        : "+f"(d[0]), "+f"(d[1]), "+f"(d[2]), "+f"(d[3])
        : "r"(a[0]), "r"(a[1]), "r"(a[2]), "r"(a[3]), "r"(b0), "r"(b1));
}
__device__ __forceinline__ void mma_f16(float* d, const uint32_t* a, uint32_t b0, uint32_t b1) {
    asm volatile("mma.sync.aligned.m16n8k16.row.col.f32.f16.f16.f32 "
        "{%0,%1,%2,%3}, {%4,%5,%6,%7}, {%8,%9}, {%0,%1,%2,%3};"
        : "+f"(d[0]), "+f"(d[1]), "+f"(d[2]), "+f"(d[3])
        : "r"(a[0]), "r"(a[1]), "r"(a[2]), "r"(a[3]), "r"(b0), "r"(b1));
}

// ---------------- fp32 -> bf16 / fp16 splits ----------------
__device__ __forceinline__ void split4_bf(const float* v, uint2& ph, uint2& pl) {
    unsigned short h[4], l[4];
#pragma unroll
    for (int j = 0; j < 4; j++) {
        __nv_bfloat16 hb = __float2bfloat16(v[j]);
        float r = v[j] - __bfloat162float(hb);
        __nv_bfloat16 lb = __float2bfloat16(r);
        h[j] = *(unsigned short*)&hb;
        l[j] = *(unsigned short*)&lb;
    }
    ph.x = (uint32_t)h[0] | ((uint32_t)h[1] << 16);
    ph.y = (uint32_t)h[2] | ((uint32_t)h[3] << 16);
    pl.x = (uint32_t)l[0] | ((uint32_t)l[1] << 16);
    pl.y = (uint32_t)l[2] | ((uint32_t)l[3] << 16);
}
__device__ __forceinline__ void split4_hf(const float* v, uint2& ph, uint2& pl) {
    unsigned short h[4], l[4];
#pragma unroll
    for (int j = 0; j < 4; j++) {
        __half hb = __float2half_rn(v[j]);
        float r = v[j] - __half2float(hb);
        __half lb = __float2half_rn(r);
        h[j] = *(unsigned short*)&hb;
        l[j] = *(unsigned short*)&lb;
    }
    ph.x = (uint32_t)h[0] | ((uint32_t)h[1] << 16);
    ph.y = (uint32_t)h[2] | ((uint32_t)h[3] << 16);
    pl.x = (uint32_t)l[0] | ((uint32_t)l[1] << 16);
    pl.y = (uint32_t)l[2] | ((uint32_t)l[3] << 16);
}

__device__ __forceinline__ uint2 pack4_hf(const float* v) {
    __half2 a = __floats2half2_rn(v[0], v[1]);
    __half2 b = __floats2half2_rn(v[2], v[3]);
    return make_uint2(*(uint32_t*)&a, *(uint32_t*)&b);
}

// hs -> bf16 hi/lo + fp16 hi/lo (one read)
__global__ void k_cvt_hs(const float4* __restrict__ src, uint2* __restrict__ bh,
                         uint2* __restrict__ bl, uint2* __restrict__ fh,
                         uint2* __restrict__ fl, int n4)
{
    int i = blockIdx.x * 256 + threadIdx.x;
    if (i >= n4) return;
    float4 v = src[i];
    float a[4] = {v.x, v.y, v.z, v.w};
    uint2 ph, pl;
    split4_bf(a, ph, pl);
    bh[i] = ph;
    bl[i] = pl;
    split4_hf(a, ph, pl);
    fh[i] = ph;
    fl[i] = pl;
}

// W1 rows [0,3072) -> fp16 ; rows [3072,5120) -> fp16 gate
__global__ void k_cvt_w1(const float4* __restrict__ W1, uint2* __restrict__ w1f,
                         uint2* __restrict__ w1g)
{
    const int NV = CONVD * DD / 4;
    const int NT = (CONVD + GDIM) * DD / 4;
    int i = blockIdx.x * 256 + threadIdx.x;
    if (i >= NT) return;
    float4 v = W1[i];
    float a[4] = {v.x, v.y, v.z, v.w};
    if (i < NV) w1f[i] = pack4_hf(a);
    else        w1g[i - NV] = pack4_hf(a);
}

__global__ void k_cvt_pad(const float4* __restrict__ src, uint2* __restrict__ hi,
                          uint2* __restrict__ lo, int n4s, int n4d)
{
    int i = blockIdx.x * 256 + threadIdx.x;
    if (i >= n4d) return;
    uint2 ph = make_uint2(0u, 0u), pl = make_uint2(0u, 0u);
    if (i < n4s) {
        float4 v = src[i];
        float a[4] = {v.x, v.y, v.z, v.w};
        split4_bf(a, ph, pl);
    }
    hi[i] = ph;
    lo[i] = pl;
}

__global__ void k_cvt_h(const float4* __restrict__ src, uint2* __restrict__ hi, int n4)
{
    int i = blockIdx.x * 256 + threadIdx.x;
    if (i >= n4) return;
    float4 v = src[i];
    float a[4] = {v.x, v.y, v.z, v.w};
    hi[i] = pack4_hf(a);
}

// ---------------- gemm1_bf: 2-mode (bf16 3-pass / fp16 1-pass) ----
// grid (17, 32).
//   bx 0..15 : gate -> fp16 1-pass (mode 1), proj cols [3072 + bx*128)
//   bx 16    : dt   -> bf16 3-pass (mode 0) + fused softplus -> g_dt
#define STAGE1 65536
#define NSTG1 3

__global__ void __launch_bounds__(256) gemm1_bf(
    const __nv_bfloat16* __restrict__ Ahb, const __nv_bfloat16* __restrict__ Alb,
    const __half* __restrict__ Ahf,
    const __half* __restrict__ W1g,
    const __nv_bfloat16* __restrict__ Wdth, const __nv_bfloat16* __restrict__ Wdtl,
    const float* __restrict__ dt_bias,
    float* __restrict__ C)
{
    extern __shared__ char smem[];
    const int t = threadIdx.x;
    const int lane = t & 31;
    const int w = t >> 5;
    const int wm = w >> 2;
    const int wn = w & 3;
    const int bx = blockIdx.x;
    const int m0 = blockIdx.y * 128;
    uint32_t sbase = smem_u32(smem);

    const int mode = (bx == 16) ? 0 : 1;
    int col0 = CONVD + bx * 128;
    const __nv_bfloat16 *Bh = nullptr, *Bl = nullptr;
    const __half *Bf = nullptr;
    if (mode == 0) { Bh = Wdth; Bl = Wdtl; }
    else           { Bf = W1g + (size_t)bx * 128 * DD; }

    const int mbase = wm * 64 + (lane & 15);
    const uint32_t a_k16 = (uint32_t)((lane >> 4) << 4);
    uint32_t a_off[4];
#pragma unroll
    for (int mt = 0; mt < 4; mt++) a_off[mt] = (uint32_t)((mbase + mt * 16) * 128);
    const uint32_t a_swz = (uint32_t)((mbase & 7) << 4);

    const int nbase = wn * 32 + (lane & 7) + ((lane >> 4) << 3);
    const uint32_t b_k16 = (uint32_t)(((lane >> 3) & 1) << 4);
    uint32_t b_off[2] = {(uint32_t)(nbase * 128), (uint32_t)((nbase + 16) * 128)};
    const uint32_t b_swz = (uint32_t)((nbase & 7) << 4);

    float acc[4][4][4];
#pragma unroll
    for (int i = 0; i < 4; i++)
#pragma unroll
        for (int j = 0; j < 4; j++)
#pragma unroll
            for (int r = 0; r < 4; r++) acc[i][j][r] = 0.f;

    const int NIT = DD >> 6;

    auto load_st = [&](uint32_t sb, int k0) {
#pragma unroll
        for (int u = 0; u < 4; u++) {
            int idx = t + u * 256;
            int row = idx >> 3, c16 = idx & 7;
            uint32_t so = (uint32_t)(row * 128) + (uint32_t)((c16 * 16) ^ ((row & 7) << 4));
            size_t gA = (size_t)(m0 + row) * DD + k0 + c16 * 8;
            size_t gB = (size_t)row * DD + k0 + c16 * 8;
            if (mode == 0) {
                cpa16(sb + so,         Ahb + gA);
                cpa16(sb + 16384 + so, Alb + gA);
                cpa16(sb + 32768 + so, Bh + gB);
                cpa16(sb + 49152 + so, Bl + gB);
            } else {
                cpa16(sb + so,         Ahf + gA);
                cpa16(sb + 32768 + so, Bf + gB);
            }
        }
    };

#pragma unroll
    for (int p = 0; p < NSTG1 - 1; p++) {
        load_st(sbase + p * STAGE1, p * 64);
        CP_COMMIT();
    }

    uint32_t ah[2][4][4], al[2][4][4], bh[2][2][4], bl[2][2][4];

    auto ldsm_frags = [&](int buf, uint32_t sb, int ks) {
        const uint32_t ka = ((uint32_t)(ks * 32) + a_k16) ^ a_swz;
        const uint32_t kb = ((uint32_t)(ks * 32) + b_k16) ^ b_swz;
#pragma unroll
        for (int mt = 0; mt < 4; mt++) LDSM4(ah[buf][mt], sb + a_off[mt] + ka);
        if (mode == 0) {
#pragma unroll
            for (int mt = 0; mt < 4; mt++) LDSM4(al[buf][mt], sb + 16384 + a_off[mt] + ka);
        }
#pragma unroll
        for (int n2 = 0; n2 < 2; n2++) LDSM4(bh[buf][n2], sb + 32768 + b_off[n2] + kb);
        if (mode == 0) {
#pragma unroll
            for (int n2 = 0; n2 < 2; n2++) LDSM4(bl[buf][n2], sb + 49152 + b_off[n2] + kb);
        }
    };
    auto mmas = [&](int buf) {
        if (mode == 0) {
#pragma unroll
            for (int mt = 0; mt < 4; mt++)
#pragma unroll
                for (int nt = 0; nt < 4; nt++)
                    mma_bf16(acc[mt][nt], ah[buf][mt], bh[buf][nt >> 1][(nt & 1) * 2], bh[buf][nt >> 1][(nt & 1) * 2 + 1]);
#pragma unroll
            for (int mt = 0; mt < 4; mt++)
#pragma unroll
                for (int nt = 0; nt < 4; nt++)
                    mma_bf16(acc[mt][nt], ah[buf][mt], bl[buf][nt >> 1][(nt & 1) * 2], bl[buf][nt >> 1][(nt & 1) * 2 + 1]);
#pragma unroll
            for (int mt = 0; mt < 4; mt++)
#pragma unroll
                for (int nt = 0; nt < 4; nt++)
                    mma_bf16(acc[mt][nt], al[buf][mt], bh[buf][nt >> 1][(nt & 1) * 2], bh[buf][nt >> 1][(nt & 1) * 2 + 1]);
        } else {
#pragma unroll
            for (int mt = 0; mt < 4; mt++)
#pragma unroll
                for (int nt = 0; nt < 4; nt++)
                    mma_f16(acc[mt][nt], ah[buf][mt], bh[buf][nt >> 1][(nt & 1) * 2], bh[buf][nt >> 1][(nt & 1) * 2 + 1]);
        }
    };

    for (int it = 0; it < NIT; ++it) {
        CP_WAIT(NSTG1 - 2);
        __syncthreads();
        if (it + NSTG1 - 1 < NIT)
            load_st(sbase + ((it + NSTG1 - 1) % NSTG1) * STAGE1, (it + NSTG1 - 1) * 64);
        CP_COMMIT();

        uint32_t sb = sbase + (it % NSTG1) * STAGE1;
        ldsm_frags(0, sb, 0);
#pragma unroll
        for (int ks = 0; ks < 4; ks++) {
            if (ks < 3) ldsm_frags((ks + 1) & 1, sb, ks + 1);
            mmas(ks & 1);
        }
    }

    const int group = lane >> 2, tid4 = lane & 3;
    if (mode == 0) {
        // fused dt epilogue: softplus(val + dt_bias) -> g_dt [bl, h]; only cols < 32
        if (wn == 0) {
#pragma unroll
            for (int mt = 0; mt < 4; mt++) {
                int row = m0 + wm * 64 + mt * 16 + group;
#pragma unroll
                for (int nt = 0; nt < 4; nt++) {
                    int c = nt * 8 + tid4 * 2;   // 0..30
                    float b0 = dt_bias[c], b1 = dt_bias[c + 1];
                    float v00 = acc[mt][nt][0] + b0, v01 = acc[mt][nt][1] + b1;
                    float v10 = acc[mt][nt][2] + b0, v11 = acc[mt][nt][3] + b1;
                    v00 = (v00 > 20.f) ? v00 : log1pf(expf(v00));
                    v01 = (v01 > 20.f) ? v01 : log1pf(expf(v01));
                    v10 = (v10 > 20.f) ? v10 : log1pf(expf(v10));
                    v11 = (v11 > 20.f) ? v11 : log1pf(expf(v11));
                    g_dt[(size_t)row * HH + c]           = v00;
                    g_dt[(size_t)row * HH + c + 1]       = v01;
                    g_dt[(size_t)(row + 8) * HH + c]     = v10;
                    g_dt[(size_t)(row + 8) * HH + c + 1] = v11;
                }
            }
        }
    } else {
#pragma unroll
        for (int mt = 0; mt < 4; mt++) {
            int row = m0 + wm * 64 + mt * 16 + group;
#pragma unroll
            for (int nt = 0; nt < 4; nt++) {
                int col = col0 + wn * 32 + nt * 8 + tid4 * 2;
                *(float2*)(C + (size_t)row * PROJP + col) = make_float2(acc[mt][nt][0], acc[mt][nt][1]);
                *(float2*)(C + (size_t)(row + 8) * PROJP + col) = make_float2(acc[mt][nt][2], acc[mt][nt][3]);
            }
        }
    }
}

// ---------------- gemm1_f16: fp16 2-pass for v,k,q tiles (cols [0,3072)) ----------
// grid (24, 32). col0 = bx*128.
#define STAGEF 49152
#define NSTGF 4

__global__ void __launch_bounds__(256) gemm1_f16(
    const __half* __restrict__ Ah, const __half* __restrict__ Al,
    const __half* __restrict__ W1f, float* __restrict__ C)
{
    extern __shared__ char smem[];
    const int t = threadIdx.x;
    const int lane = t & 31;
    const int w = t >> 5;
    const int wm = w >> 2;
    const int wn = w & 3;
    const int m0 = blockIdx.y * 128;
    const int col0 = blockIdx.x * 128;
    const __half* Bh = W1f + (size_t)blockIdx.x * 128 * DD;
    uint32_t sbase = smem_u32(smem);

    const int mbase = wm * 64 + (lane & 15);
    const uint32_t a_k16 = (uint32_t)((lane >> 4) << 4);
    uint32_t a_off[4];
#pragma unroll
    for (int mt = 0; mt < 4; mt++) a_off[mt] = (uint32_t)((mbase + mt * 16) * 128);
    const uint32_t a_swz = (uint32_t)((mbase & 7) << 4);

    const int nbase = wn * 32 + (lane & 7) + ((lane >> 4) << 3);
    const uint32_t b_k16 = (uint32_t)(((lane >> 3) & 1) << 4);
    uint32_t b_off[2] = {(uint32_t)(nbase * 128), (uint32_t)((nbase + 16) * 128)};
    const uint32_t b_swz = (uint32_t)((nbase & 7) << 4);

    float acc[4][4][4];
#pragma unroll
    for (int i = 0; i < 4; i++)
#pragma unroll
        for (int j = 0; j < 4; j++)
#pragma unroll
            for (int r = 0; r < 4; r++) acc[i][j][r] = 0.f;

    const int NIT = DD >> 6;

    auto load_st = [&](uint32_t sb, int k0) {
#pragma unroll
        for (int u = 0; u < 4; u++) {
            int idx = t + u * 256;
            int row = idx >> 3, c16 = idx & 7;
            uint32_t so = (uint32_t)(row * 128) + (uint32_t)((c16 * 16) ^ ((row & 7) << 4));
            size_t gA = (size_t)(m0 + row) * DD + k0 + c16 * 8;
            size_t gB = (size_t)row * DD + k0 + c16 * 8;
            cpa16(sb + so,         Ah + gA);
            cpa16(sb + 16384 + so, Al + gA);
            cpa16(sb + 32768 + so, Bh + gB);
        }
    };

#pragma unroll
    for (int p = 0; p < NSTGF - 1; p++) {
        load_st(sbase + p * STAGEF, p * 64);
        CP_COMMIT();
    }

    uint32_t ah[2][4][4], al[2][4][4], bh[2][2][4];

    auto ldsm_frags = [&](int buf, uint32_t sb, int ks) {
        const uint32_t ka = ((uint32_t)(ks * 32) + a_k16) ^ a_swz;
        const uint32_t kb = ((uint32_t)(ks * 32) + b_k16) ^ b_swz;
#pragma unroll
        for (int mt = 0; mt < 4; mt++) LDSM4(ah[buf][mt], sb + a_off[mt] + ka);
#pragma unroll
        for (int mt = 0; mt < 4; mt++) LDSM4(al[buf][mt], sb + 16384 + a_off[mt] + ka);
#pragma unroll
        for (int n2 = 0; n2 < 2; n2++) LDSM4(bh[buf][n2], sb + 32768 + b_off[n2] + kb);
    };
    auto mmas = [&](int buf) {
#pragma unroll
        for (int mt = 0; mt < 4; mt++)
#pragma unroll
            for (int nt = 0; nt < 4; nt++)
                mma_f16(acc[mt][nt], ah[buf][mt], bh[buf][nt >> 1][(nt & 1) * 2], bh[buf][nt >> 1][(nt & 1) * 2 + 1]);
#pragma unroll
        for (int mt = 0; mt < 4; mt++)
#pragma unroll
            for (int nt = 0; nt < 4; nt++)
                mma_f16(acc[mt][nt], al[buf][mt], bh[buf][nt >> 1][(nt & 1) * 2], bh[buf][nt >> 1][(nt & 1) * 2 + 1]);
    };

    for (int it = 0; it < NIT; ++it) {
        CP_WAIT(NSTGF - 2);
        __syncthreads();
        if (it + NSTGF - 1 < NIT)
            load_st(sbase + ((it + NSTGF - 1) % NSTGF) * STAGEF, (it + NSTGF - 1) * 64);
        CP_COMMIT();

        uint32_t sb = sbase + (it % NSTGF) * STAGEF;
        ldsm_frags(0, sb, 0);
#pragma unroll
        for (int ks = 0; ks < 4; ks++) {
            if (ks < 3) ldsm_frags((ks + 1) & 1, sb, ks + 1);
            mmas(ks & 1);
        }
    }

    const int group = lane >> 2, tid4 = lane & 3;
#pragma unroll
    for (int mt = 0; mt < 4; mt++) {
        int row = m0 + wm * 64 + mt * 16 + group;
#pragma unroll
        for (int nt = 0; nt < 4; nt++) {
            int col = col0 + wn * 32 + nt * 8 + tid4 * 2;
            *(float2*)(C + (size_t)row * PROJP + col) = make_float2(acc[mt][nt][0], acc[mt][nt][1]);
            *(float2*)(C + (size_t)(row + 8) * PROJP + col) = make_float2(acc[mt][nt][2], acc[mt][nt][3]);
        }
    }
}

// ---------------- gemm2: fp16 1-pass ----------------
#define STAGE2 32768
#define NSTG2 5

__global__ void __launch_bounds__(256) gemm2(
    const __half* __restrict__ Ah, const __half* __restrict__ Bh, float* __restrict__ C)
{
    extern __shared__ char smem[];
    const int t = threadIdx.x;
    const int lane = t & 31;
    const int w = t >> 5;
    const int wm = w >> 2;
    const int wn = w & 3;
    const int m0 = blockIdx.y * 128;
    const int n0 = blockIdx.x * 128;
    uint32_t sbase = smem_u32(smem);

    const int mbase = wm * 64 + (lane & 15);
    const uint32_t a_k16 = (uint32_t)((lane >> 4) << 4);
    uint32_t a_off[4];
#pragma unroll
    for (int mt = 0; mt < 4; mt++) a_off[mt] = (uint32_t)((mbase + mt * 16) * 128);
    const uint32_t a_swz = (uint32_t)((mbase & 7) << 4);

    const int nbase = wn * 32 + (lane & 7) + ((lane >> 4) << 3);
    const uint32_t b_k16 = (uint32_t)(((lane >> 3) & 1) << 4);
    uint32_t b_off[2] = {(uint32_t)(nbase * 128), (uint32_t)((nbase + 16) * 128)};
    const uint32_t b_swz = (uint32_t)((nbase & 7) << 4);

    float acc[4][4][4];
#pragma unroll
    for (int i = 0; i < 4; i++)
#pragma unroll
        for (int j = 0; j < 4; j++)
#pragma unroll
            for (int r = 0; r < 4; r++) acc[i][j][r] = 0.f;

    const int NIT = DD >> 6;

    auto load_st = [&](uint32_t sb, int k0) {
#pragma unroll
        for (int u = 0; u < 4; u++) {
            int idx = t + u * 256;
            int row = idx >> 3, c16 = idx & 7;
            uint32_t so = (uint32_t)(row * 128) + (uint32_t)((c16 * 16) ^ ((row & 7) << 4));
            size_t gA = (size_t)(m0 + row) * DD + k0 + c16 * 8;
            size_t gB = (size_t)(n0 + row) * DD + k0 + c16 * 8;
            cpa16(sb + so,         Ah + gA);
            cpa16(sb + 16384 + so, Bh + gB);
        }
    };

#pragma unroll
    for (int p = 0; p < NSTG2 - 1; p++) {
        load_st(sbase + p * STAGE2, p * 64);
        CP_COMMIT();
    }

    uint32_t ah[2][4][4], bh[2][2][4];

    auto ldsm_frags = [&](int buf, uint32_t sb, int ks) {
        const uint32_t ka = ((uint32_t)(ks * 32) + a_k16) ^ a_swz;
        const uint32_t kb = ((uint32_t)(ks * 32) + b_k16) ^ b_swz;
#pragma unroll
        for (int mt = 0; mt < 4; mt++) LDSM4(ah[buf][mt], sb + a_off[mt] + ka);
#pragma unroll
        for (int n2 = 0; n2 < 2; n2++) LDSM4(bh[buf][n2], sb + 16384 + b_off[n2] + kb);
    };
    auto mmas = [&](int buf) {
#pragma unroll
        for (int mt = 0; mt < 4; mt++)
#pragma unroll
            for (int nt = 0; nt < 4; nt++)
                mma_f16(acc[mt][nt], ah[buf][mt], bh[buf][nt >> 1][(nt & 1) * 2], bh[buf][nt >> 1][(nt & 1) * 2 + 1]);
    };

    for (int it = 0; it < NIT; ++it) {
        CP_WAIT(NSTG2 - 2);
        __syncthreads();
        if (it + NSTG2 - 1 < NIT)
            load_st(sbase + ((it + NSTG2 - 1) % NSTG2) * STAGE2, (it + NSTG2 - 1) * 64);
        CP_COMMIT();

        uint32_t sb = sbase + (it % NSTG2) * STAGE2;
        ldsm_frags(0, sb, 0);
#pragma unroll
        for (int ks = 0; ks < 4; ks++) {
            if (ks < 3) ldsm_frags((ks + 1) & 1, sb, ks + 1);
            mmas(ks & 1);
        }
    }

    const int group = lane >> 2, tid4 = lane & 3;
#pragma unroll
    for (int mt = 0; mt < 4; mt++) {
        int row = m0 + wm * 64 + mt * 16 + group;
#pragma unroll
        for (int nt = 0; nt < 4; nt++) {
            int col = n0 + wn * 32 + nt * 8 + tid4 * 2;
            *(float2*)(C + (size_t)row * DD + col) = make_float2(acc[mt][nt][0], acc[mt][nt][1]);
            *(float2*)(C + (size_t)(row + 8) * DD + col) = make_float2(acc[mt][nt][2], acc[mt][nt][3]);
        }
    }
}

// ---------------- depthwise conv(k=2) + SiLU + route splits (vectorized x4) ----------------
__global__ void k_conv(const float* __restrict__ cw, const float* __restrict__ cb)
{
    const int C4 = CONVD / 4;   // 768
    int tid = blockIdx.x * 256 + threadIdx.x;
    if (tid >= BL * C4) return;
    int c = (tid % C4) * 4;
    int bl = tid / C4;
    int l = bl & (LL - 1);
    float4 cur = *(const float4*)(g_proj + (size_t)bl * PROJP + c);
    float4 prev = l ? *(const float4*)(g_proj + (size_t)(bl - 1) * PROJP + c)
                    : make_float4(0.f, 0.f, 0.f, 0.f);
    float4 w0 = *(const float4*)(cw + 2 * c);
    float4 w1 = *(const float4*)(cw + 2 * c + 4);
    float4 bb = *(const float4*)(cb + c);
    float v[4];
    v[0] = prev.x * w0.x + cur.x * w0.y + bb.x;
    v[1] = prev.y * w0.z + cur.y * w0.w + bb.y;
    v[2] = prev.z * w1.x + cur.z * w1.y + bb.z;
    v[3] = prev.w * w1.z + cur.w * w1.w + bb.w;
#pragma unroll
    for (int j = 0; j < 4; j++) v[j] = v[j] / (1.f + expf(-v[j]));

    if (c < KVHN * PP) {                       // v channels
        int kv = c >> 6, p = c & 63;
#pragma unroll
        for (int g = 0; g < 4; g++) {
            int h = kv * 4 + g;
            float dt = g_dt[(size_t)bl * HH + h];
            *(float4*)(g_x + ((size_t)bl * HH + h) * PP + p) =
                make_float4(v[0] * dt, v[1] * dt, v[2] * dt, v[3] * dt);
        }
    } else if (c < 2 * KVHN * PP) {            // k channels
        int cc = c - KVHN * PP;
        int kv = cc >> 6, p = cc & 63;
        *(float4*)(g_k + ((size_t)bl * KVHN + kv) * PP + p) =
            make_float4(v[0], v[1], v[2], v[3]);
    } else {                                   // q channels
        int cc = c - 2 * KVHN * PP;
        int h = cc >> 6, p = cc & 63;
        *(float4*)(g_q + ((size_t)bl * HH + h) * PP + p) =
            make_float4(v[0], v[1], v[2], v[3]);
    }
}

// ---------------- per-chunk cumsum of A*dt ----------------
__global__ void k_cumsum(const float* __restrict__ A_log_bias)
{
    int w = blockIdx.x * 8 + (threadIdx.x >> 5);
    int lane = threadIdx.x & 31;
    int c = w % NCH;
    int bh = w / NCH;
    int h = bh % HH;
    int b = bh / HH;
    float Ahv = -expf(A_log_bias[h]);
    int bl0 = b * LL + c * CHUNK;
    float v[4];
    float s = 0.f;
#pragma unroll
    for (int j = 0; j < 4; j++) {
        v[j] = g_dt[(size_t)(bl0 + lane * 4 + j) * HH + h] * Ahv;
        s += v[j];
    }
    float run = s;
#pragma unroll
    for (int d = 1; d < 32; d <<= 1) {
        float o = __shfl_up_sync(0xffffffffu, run, d);
        if (lane >= d) run += o;
    }
    float acc = run - s;
#pragma unroll
    for (int j = 0; j < 4; j++) {
        acc += v[j];
        g_acs[(size_t)(bl0 + lane * 4 + j) * HH + h] = acc;
    }
    if (lane == 31) g_cdecay[(b * HH + h) * NCH + c] = expf(acc);
}

// ---------------- Phase A: intra-chunk attention + chunk states ----------------
__global__ void __launch_bounds__(256) k_intra()
{
    extern __shared__ float sm[];
    float* sqT  = sm;
    float* skT  = sqT + 64 * 132;
    float* sS   = skT + 64 * 132;
    float* sx   = sS + 128 * 132;
    float* sacs = sx + 128 * 68;
    float* sei  = sacs + 128;
    float* sr   = sei + 128;
    float* sd   = sr + 128;

    const int t = threadIdx.x;
    const int h = blockIdx.x;
    const int c = blockIdx.y;
    const int b = blockIdx.z;
    const int bl0 = b * LL + c * CHUNK;
    const int kv = h >> 2;

    {
        int i = t >> 1;
        int n0 = (t & 1) * 32;
        const float* qp = g_q + ((size_t)(bl0 + i) * HH + h) * PP + n0;
        const float* kp = g_k + ((size_t)(bl0 + i) * KVHN + kv) * PP + n0;
        const float* xp = g_x + ((size_t)(bl0 + i) * HH + h) * PP + n0;
#pragma unroll
        for (int s = 0; s < 32; s += 4) {
            float4 vq = *(const float4*)(qp + s);
            sqT[(n0+s+0)*132 + i] = vq.x; sqT[(n0+s+1)*132 + i] = vq.y;
            sqT[(n0+s+2)*132 + i] = vq.z; sqT[(n0+s+3)*132 + i] = vq.w;
            float4 vk = *(const float4*)(kp + s);
            skT[(n0+s+0)*132 + i] = vk.x; skT[(n0+s+1)*132 + i] = vk.y;
            skT[(n0+s+2)*132 + i] = vk.z; skT[(n0+s+3)*132 + i] = vk.w;
            *(float4*)&sx[i * 68 + n0 + s] = *(const float4*)(xp + s);
        }
        if (t < 128) sacs[t] = g_acs[(size_t)(bl0 + t) * HH + h];
    }
    __syncthreads();
    if (t < 128) {
        float a = sacs[t];
        sei[t] = expf(a);
        sr[t]  = expf(fminf(-a, 80.f));
        sd[t]  = expf(sacs[127] - a);
    }
    __syncthreads();

    {
        const int i0 = (t >> 4) * 8;
        const int j0 = (t & 15) * 8;
        float accS[8][8];
#pragma unroll
        for (int i = 0; i < 8; i++)
#pragma unroll
            for (int j = 0; j < 8; j++) accS[i][j] = 0.f;
#pragma unroll 8
        for (int kk = 0; kk < 64; kk++) {
            float ar[8], br[8];
            *(float4*)(ar)     = *(const float4*)&sqT[kk * 132 + i0];
            *(float4*)(ar + 4) = *(const float4*)&sqT[kk * 132 + i0 + 4];
            *(float4*)(br)     = *(const float4*)&skT[kk * 132 + j0];
            *(float4*)(br + 4) = *(const float4*)&skT[kk * 132 + j0 + 4];
#pragma unroll
            for (int i = 0; i < 8; i++)
#pragma unroll
                for (int j = 0; j < 8; j++)
                    accS[i][j] = fmaf(ar[i], br[j], accS[i][j]);
        }
#pragma unroll
        for (int ii = 0; ii < 8; ii++) {
            int i = i0 + ii;
            float e_i = sei[i];
#pragma unroll
            for (int jj = 0; jj < 8; jj++) {
                int j = j0 + jj;
                sS[i * 132 + j] = (j <= i) ? accS[ii][jj] * e_i * sr[j] : 0.f;
            }
        }
    }
    __syncthreads();

    {
        const int i0 = (t >> 4) * 8;
        const int p0 = (t & 15) * 4;
        const int jmax = i0 + 8;   // strictly causal clamp
        float accY[8][4];
#pragma unroll
        for (int i = 0; i < 8; i++)
#pragma unroll
            for (int j = 0; j < 4; j++) accY[i][j] = 0.f;
#pragma unroll 4
        for (int j = 0; j < jmax; j++) {
            float4 xv = *(const float4*)&sx[j * 68 + p0];
#pragma unroll
            for (int ii = 0; ii < 8; ii++) {
                float s = sS[(i0 + ii) * 132 + j];
                accY[ii][0] = fmaf(s, xv.x, accY[ii][0]);
                accY[ii][1] = fmaf(s, xv.y, accY[ii][1]);
                accY[ii][2] = fmaf(s, xv.z, accY[ii][2]);
                accY[ii][3] = fmaf(s, xv.w, accY[ii][3]);
            }
        }
#pragma unroll
        for (int ii = 0; ii < 8; ii++) {
            *(float4*)(g_y + ((size_t)(bl0 + i0 + ii) * HH + h) * PP + p0) =
                make_float4(accY[ii][0], accY[ii][1], accY[ii][2], accY[ii][3]);
        }
    }

    {
        const int n0 = (t >> 4) * 4;
        const int p0 = (t & 15) * 4;
        float accT[4][4];
#pragma unroll
        for (int i = 0; i < 4; i++)
#pragma unroll
            for (int j = 0; j < 4; j++) accT[i][j] = 0.f;
#pragma unroll 4
        for (int j = 0; j < 128; j++) {
            float dj = sd[j];
            float4 xv = *(const float4*)&sx[j * 68 + p0];
            float xd[4] = {xv.x * dj, xv.y * dj, xv.z * dj, xv.w * dj};
#pragma unroll
            for (int nn = 0; nn < 4; nn++) {
                float kvv = skT[(n0 + nn) * 132 + j];
                accT[nn][0] = fmaf(kvv, xd[0], accT[nn][0]);
                accT[nn][1] = fmaf(kvv, xd[1], accT[nn][1]);
                accT[nn][2] = fmaf(kvv, xd[2], accT[nn][2]);
                accT[nn][3] = fmaf(kvv, xd[3], accT[nn][3]);
            }
        }
        size_t base = (((size_t)(b * NCH + c) * HH + h) << 12);
#pragma unroll
        for (int nn = 0; nn < 4; nn++) {
            *(float4*)(g_states + base + (size_t)(n0 + nn) * PP + p0) =
                make_float4(accT[nn][0], accT[nn][1], accT[nn][2], accT[nn][3]);
        }
    }
}

// ---------------- Phase B: inter-chunk state scan (1 chain / thread) ----------------
__global__ void k_scan()
{
    const int e = blockIdx.x * 256 + threadIdx.x;   // 0..4095
    const int h = blockIdx.y;
    const int b = blockIdx.z;
    const float* dec = g_cdecay + (b * HH + h) * NCH;
    float run = 0.f;
#pragma unroll
    for (int c = 0; c < NCH; c++) {
        size_t off = (((size_t)(b * NCH + c) * HH + h) << 12) + e;
        g_prefix[off] = run;
        run = run * dec[c] + g_states[off];
    }
}

// ---------------- Phase C: inter-chunk output + RMSNorm + gate (emit fp16) ----------------
__global__ void __launch_bounds__(256) k_inter(const float* __restrict__ gnw)
{
    __shared__ float spref[64 * 64];
    __shared__ float sacs[128];
    const int t = threadIdx.x;
    const int h = blockIdx.x;
    const int c = blockIdx.y;
    const int b = blockIdx.z;
    const int bl0 = b * LL + c * CHUNK;
    size_t pbase = (((size_t)(b * NCH + c) * HH + h) << 12);
    for (int e = t; e < 4096; e += 256) spref[e] = g_prefix[pbase + e];
    if (t < 128) sacs[t] = g_acs[(size_t)(bl0 + t) * HH + h];
    __syncthreads();

    const int i = t >> 1;
    const int p0 = (t & 1) * 32;
    const int bl = bl0 + i;
    const float4* qp = (const float4*)(g_q + ((size_t)bl * HH + h) * PP);

    float acc[32];
#pragma unroll
    for (int pp = 0; pp < 32; pp++) acc[pp] = 0.f;
#pragma unroll
    for (int nb = 0; nb < 16; nb++) {
        float4 qv = qp[nb];
        float qa[4] = {qv.x, qv.y, qv.z, qv.w};
#pragma unroll
        for (int e = 0; e < 4; e++) {
            const float* pr = &spref[(nb * 4 + e) * 64 + p0];
#pragma unroll
            for (int pp = 0; pp < 32; pp += 4) {
                float4 pv = *(const float4*)(pr + pp);
                acc[pp+0] = fmaf(qa[e], pv.x, acc[pp+0]);
                acc[pp+1] = fmaf(qa[e], pv.y, acc[pp+1]);
                acc[pp+2] = fmaf(qa[e], pv.z, acc[pp+2]);
                acc[pp+3] = fmaf(qa[e], pv.w, acc[pp+3]);
            }
        }
    }

    float ei = expf(sacs[i]);
    const float4* ydp = (const float4*)(g_y + ((size_t)bl * HH + h) * PP + p0);
    float y[32];
    float ss = 0.f;
#pragma unroll
    for (int pp = 0; pp < 32; pp += 4) {
        float4 yv = ydp[pp >> 2];
        y[pp+0] = yv.x + ei * acc[pp+0];
        y[pp+1] = yv.y + ei * acc[pp+1];
        y[pp+2] = yv.z + ei * acc[pp+2];
        y[pp+3] = yv.w + ei * acc[pp+3];
        ss += y[pp+0]*y[pp+0] + y[pp+1]*y[pp+1] + y[pp+2]*y[pp+2] + y[pp+3]*y[pp+3];
    }
    ss += __shfl_xor_sync(0xffffffffu, ss, 1);
    float scale = rsqrtf(ss * (1.f / 64.f) + 1e-5f);

    const float* gp = g_proj + (size_t)bl * PROJP + CONVD + h * PP + p0;
    size_t obase = (size_t)bl * DD + h * PP + p0;
#pragma unroll
    for (int pp = 0; pp < 32; pp += 4) {
        float ov[4];
#pragma unroll
        for (int j = 0; j < 4; j++) {
            float gv = gp[pp + j];
            float sg = gv / (1.f + expf(-gv));
            ov[j] = y[pp + j] * scale * gnw[p0 + pp + j] * sg;
        }
        *(uint2*)(g_ygh + obase + pp) = pack4_hf(ov);
    }
}

// ---------------- launch ----------------
extern "C" void kernel_launch(void* const* d_in, const int* in_sizes, int n_in,
                              void* d_out, int out_size)
{
    const float* hs       = (const float*)d_in[0];
    const float* W1       = (const float*)d_in[1];
    const float* conv_w   = (const float*)d_in[2];
    const float* conv_b   = (const float*)d_in[3];
    const float* dt_bias  = (const float*)d_in[4];
    const float* A_logb   = (const float*)d_in[5];
    const float* gnorm_w  = (const float*)d_in[6];
    const float* W_o      = (const float*)d_in[7];
    float* out = (float*)d_out;

    float *p_proj;
    __nv_bfloat16 *p_hsh, *p_hsl, *p_wdth, *p_wdtl;
    __half *p_hsf, *p_hsfl, *p_w1f, *p_w1g, *p_woh, *p_ygh;
    cudaGetSymbolAddress((void**)&p_proj, g_proj);
    cudaGetSymbolAddress((void**)&p_hsh, g_hsh);
    cudaGetSymbolAddress((void**)&p_hsl, g_hsl);
    cudaGetSymbolAddress((void**)&p_hsf, g_hsf);
    cudaGetSymbolAddress((void**)&p_hsfl, g_hsfl);
    cudaGetSymbolAddress((void**)&p_w1f, g_w1f);
    cudaGetSymbolAddress((void**)&p_w1g, g_w1g);
    cudaGetSymbolAddress((void**)&p_wdth, g_wdth);
    cudaGetSymbolAddress((void**)&p_wdtl, g_wdtl);
    cudaGetSymbolAddress((void**)&p_woh, g_woh);
    cudaGetSymbolAddress((void**)&p_ygh, g_ygh);

    cudaFuncSetAttribute(k_intra, cudaFuncAttributeMaxDynamicSharedMemorySize, 172032);
    cudaFuncSetAttribute(gemm1_bf, cudaFuncAttributeMaxDynamicSharedMemorySize, NSTG1 * STAGE1);
    cudaFuncSetAttribute(gemm1_f16, cudaFuncAttributeMaxDynamicSharedMemorySize, NSTGF * STAGEF);
    cudaFuncSetAttribute(gemm2, cudaFuncAttributeMaxDynamicSharedMemorySize, NSTG2 * STAGE2);

    // operand conversions
    k_cvt_hs<<<(BL * DD / 4 + 255) / 256, 256>>>((const float4*)hs, (uint2*)p_hsh,
                                                 (uint2*)p_hsl, (uint2*)p_hsf,
                                                 (uint2*)p_hsfl, BL * DD / 4);
    k_cvt_w1<<<((CONVD + GDIM) * DD / 4 + 255) / 256, 256>>>((const float4*)W1,
                                                 (uint2*)p_w1f, (uint2*)p_w1g);
    k_cvt_pad<<<(128 * DD / 4 + 255) / 256, 256>>>((const float4*)(W1 + (size_t)(CONVD + GDIM) * DD),
                                                   (uint2*)p_wdth, (uint2*)p_wdtl,
                                                   32 * DD / 4, 128 * DD / 4);
    k_cvt_h<<<(DD * DD / 4 + 255) / 256, 256>>>((const float4*)W_o, (uint2*)p_woh, DD * DD / 4);

    // 1a. gate + dt (2-mode, fused dt softplus)
    gemm1_bf<<<dim3(17, BL / 128), 256, NSTG1 * STAGE1>>>(
        p_hsh, p_hsl, p_hsf, p_w1g, p_wdth, p_wdtl, dt_bias, p_proj);
    // 1b. v + k + q (fp16 2-pass, cols [0,3072))
    gemm1_f16<<<dim3(24, BL / 128), 256, NSTGF * STAGEF>>>(
        p_hsf, p_hsfl, p_w1f, p_proj);

    // 2..6 SSD pipeline
    k_conv<<<(BL * (CONVD / 4) + 255) / 256, 256>>>(conv_w, conv_b);
    k_cumsum<<<128, 256>>>(A_logb);
    k_intra<<<dim3(HH, NCH, BB), 256, 172032>>>();
    k_scan<<<dim3(16, HH, BB), 256>>>();
    k_inter<<<dim3(HH, NCH, BB), 256>>>(gnorm_w);

    // 7. out = yg @ Wo^T (fp16 1-pass)
    gemm2<<<dim3(DD / 128, BL / 128), 256, NSTG2 * STAGE2>>>(p_ygh, p_woh, out);
}